// round 10
// baseline (speedup 1.0000x reference)
#include <cuda_runtime.h>
#include <cuda_bf16.h>
#include <math.h>
#include <stdint.h>

// ---------------------------------------------------------------------------
// Net_76690936037575 — bf16 mma.sync (m16n8k16), M=128 tiles, 256 threads,
// 2 CTAs/SM. R10: ldmatrix.x4 fragment loads over natural [row][k] layout
// (row pitch 68 words = 272B -> conflict-free ldmatrix phases), and the
// mlp2 scatter is staged through SMEM so global stores are row-coalesced.
// Dead-work elimination: var rows overwritten by the con scatter are skipped.
// All scalar math (layer-1, bias, ReLU, sigmoid, W4-dot) stays fp32.
// ---------------------------------------------------------------------------

#define PWW 68            // words (bf16x2) per tile row: 64 data + 4 pad
#define RB  272           // row bytes
#define TILE_B (128 * RB) // bytes per 128-row tile

// Node embeddings: 1e6 nodes x 64 words (128 bf16), natural layout. 256 MB.
__device__ uint32_t g_xbuf[64u * 1000000u];
// Transposed bf16x2 weights [n][k-word], pitch PWW:
// 0=vW2^T 1=cW2^T 2=W1^T 3=W2^T 4=W3^T
__device__ uint32_t g_wB[5][128 * PWW];
// mask[node] = 1 if node is written by the con scatter (var write is dead).
__device__ unsigned char g_mask[1000000u];

__device__ __forceinline__ uint32_t smem_u32(const void* p) {
    uint32_t a;
    asm("{ .reg .u64 t; cvta.to.shared.u64 t, %1; cvt.u32.u64 %0, t; }" : "=r"(a) : "l"(p));
    return a;
}
__device__ __forceinline__ uint32_t pack_bf16x2(float lo, float hi) {
    uint32_t r;
    asm("cvt.rn.bf16x2.f32 %0, %1, %2;" : "=r"(r) : "f"(hi), "f"(lo));
    return r;
}
__device__ __forceinline__ void mma16(float* d, const uint32_t* a, uint32_t b0, uint32_t b1) {
    asm volatile("mma.sync.aligned.m16n8k16.row.col.f32.bf16.bf16.f32 "
                 "{%0,%1,%2,%3}, {%4,%5,%6,%7}, {%8,%9}, {%0,%1,%2,%3};"
                 : "+f"(d[0]), "+f"(d[1]), "+f"(d[2]), "+f"(d[3])
                 : "r"(a[0]), "r"(a[1]), "r"(a[2]), "r"(a[3]), "r"(b0), "r"(b1));
}
__device__ __forceinline__ void ldsm4(uint32_t* r, uint32_t addr) {
    asm volatile("ldmatrix.sync.aligned.m8n8.x4.shared.b16 {%0,%1,%2,%3}, [%4];"
                 : "=r"(r[0]), "=r"(r[1]), "=r"(r[2]), "=r"(r[3]) : "r"(addr));
}

// Warp GEMM 32m x 64n x 128k via ldmatrix over natural-layout tiles.
// acc[mt][nt][c]: c0,c1 = (row g, cols 2tg,2tg+1); c2,c3 = row g+8.
__device__ __forceinline__ void gemm_frag(uint32_t As, uint32_t Bs,
                                          float acc[2][8][4],
                                          int lane, int m0w, int n0w)
{
    const int rA = m0w + (lane & 7) + ((lane >> 3) & 1) * 8;
    const uint32_t aAddr = As + rA * RB + ((lane >> 4) & 1) * 16;
    const int rB = n0w + (lane & 7) + ((lane >> 4) & 1) * 8;
    const uint32_t bAddr = Bs + rB * RB + ((lane >> 3) & 1) * 16;
#pragma unroll
    for (int kt = 0; kt < 8; kt++) {
        const uint32_t ko = kt * 32;   // 8 words = 32B per k-step
        uint32_t a0[4], a1[4], b[4][4];
        ldsm4(a0, aAddr + ko);
        ldsm4(a1, aAddr + 16 * RB + ko);
#pragma unroll
        for (int p = 0; p < 4; p++) ldsm4(b[p], bAddr + p * 16 * RB + ko);
#pragma unroll
        for (int p = 0; p < 4; p++) {
            mma16(acc[0][2 * p],     a0, b[p][0], b[p][1]);
            mma16(acc[0][2 * p + 1], a0, b[p][2], b[p][3]);
            mma16(acc[1][2 * p],     a1, b[p][0], b[p][1]);
            mma16(acc[1][2 * p + 1], a1, b[p][2], b[p][3]);
        }
    }
}

__device__ __forceinline__ void stageB(uint32_t* __restrict__ Bs,
                                       const uint32_t* __restrict__ wt, int tid)
{
    const uint4* src = (const uint4*)wt;
    uint4* dst = (uint4*)Bs;
#pragma unroll 3
    for (int i = tid; i < 128 * PWW / 4; i += 256) dst[i] = src[i];
}

// ---------------------------------------------------------------------------
// Prep: g_wB[w][n*PWW + u] = bf16x2(W[2u][n], W[2u+1][n]),  u = k-word 0..63.
// ---------------------------------------------------------------------------
extern "C" __global__ void prep_kernel(const float* __restrict__ vW2, const float* __restrict__ cW2,
                                       const float* __restrict__ W1, const float* __restrict__ W2,
                                       const float* __restrict__ W3)
{
    int idx = blockIdx.x * 256 + threadIdx.x;
    if (idx >= 5 * 128 * 64) return;
    int w = idx >> 13, e = idx & 8191;
    int nn = e >> 6, u = e & 63;
    const float* src = (w == 0) ? vW2 : (w == 1) ? cW2 : (w == 2) ? W1 : (w == 3) ? W2 : W3;
    g_wB[w][nn * PWW + u] = pack_bf16x2(src[(2 * u) * 128 + nn], src[(2 * u + 1) * 128 + nn]);
}

// Mark nodes that the con scatter will write (var writes there are dead).
extern "C" __global__ void mark_kernel(const int* __restrict__ assoc_con, int n)
{
    int i = blockIdx.x * 256 + threadIdx.x;
    if (i < n) g_mask[assoc_con[i]] = 1;
}

// ---------------------------------------------------------------------------
// mlp2_scatter: 128 rows/CTA. h = relu(f @ W1[2,128]+b1) fp32 -> bf16 tile;
// emb = h@W2+b2 -> SMEM -> row-coalesced scatter to g_xbuf[assoc].
// If maskp != 0, rows whose node is masked are dead; all-dead CTAs exit.
// ---------------------------------------------------------------------------
extern "C" __global__ void __launch_bounds__(256, 2)
mlp2_scatter_kernel(const float* __restrict__ feats, const int* __restrict__ assoc,
                    const float* __restrict__ W1g, const float* __restrict__ b1g,
                    const float* __restrict__ b2g,
                    const unsigned char* __restrict__ maskp, int n, int widx)
{
    extern __shared__ uint32_t smw[];
    uint32_t* A = smw;                           // 128*PWW words
    uint32_t* B = smw + 128 * PWW;               // 128*PWW words
    float* misc = (float*)(smw + 2 * 128 * PWW);
    float* F0  = misc;           // 128
    float* F1  = misc + 128;     // 128
    float* W1s = misc + 256;     // 256
    float* b1s = misc + 512;     // 128
    float* b2s = misc + 640;     // 128
    int*   nodes = (int*)(misc + 768);    // 128
    int*   sdead = (int*)(misc + 896);    // 128

    const int tid = threadIdx.x, lane = tid & 31, w = tid >> 5;
    const int m0 = blockIdx.x * 128;
    const int m0w = (w & 3) * 32, n0w = (w >> 2) * 64;
    const uint32_t Au = smem_u32(A), Bu = smem_u32(B);

    int mydead = 1;
    if (tid < 128) {
        int r = m0 + tid;
        int nd = (r < n) ? assoc[r] : 0;
        nodes[tid] = nd;
        mydead = (r < n) ? (maskp ? (int)maskp[nd] : 0) : 1;
        sdead[tid] = mydead;
    }
    if (__syncthreads_and(mydead)) return;   // whole tile dead

    if (tid < 256) W1s[tid] = W1g[tid];
    if (tid < 128) {
        b1s[tid] = b1g[tid];
        b2s[tid] = b2g[tid];
        int r = m0 + tid;
        float2 f = (r < n) ? ((const float2*)feats)[r] : make_float2(0.f, 0.f);
        F0[tid] = f.x; F1[tid] = f.y;
    }
    stageB(B, g_wB[widx], tid);
    __syncthreads();

    // Layer 1 (fp32) -> A natural layout. One thread = one (row, 16-k chunk).
    for (int idx = tid; idx < 128 * 8; idx += 256) {
        int m = idx >> 3, c = idx & 7, k0 = c * 16;
        float f0 = F0[m], f1 = F1[m];
        uint32_t wv[8];
#pragma unroll
        for (int u = 0; u < 8; u++) {
            int k = k0 + 2 * u;
            float h0 = fmaxf(fmaf(f0, W1s[k],     fmaf(f1, W1s[128 + k],     b1s[k])),     0.f);
            float h1 = fmaxf(fmaf(f0, W1s[k + 1], fmaf(f1, W1s[128 + k + 1], b1s[k + 1])), 0.f);
            wv[u] = pack_bf16x2(h0, h1);
        }
        uint32_t* dst = A + m * PWW + c * 8;
        *(uint4*)(dst)     = make_uint4(wv[0], wv[1], wv[2], wv[3]);
        *(uint4*)(dst + 4) = make_uint4(wv[4], wv[5], wv[6], wv[7]);
    }
    __syncthreads();

    float acc[2][8][4];
#pragma unroll
    for (int mt = 0; mt < 2; mt++)
#pragma unroll
        for (int nt = 0; nt < 8; nt++)
#pragma unroll
            for (int c = 0; c < 4; c++) acc[mt][nt][c] = 0.f;

    gemm_frag(Au, Bu, acc, lane, m0w, n0w);
    __syncthreads();   // all warps done reading A; reuse it as output staging

    // Epilogue: +b2, pack bf16x2 -> A (natural layout).
    const int g = lane >> 2, tg = lane & 3;
#pragma unroll
    for (int mt = 0; mt < 2; mt++) {
        int row0 = m0w + 16 * mt + g;
        uint32_t* a0 = A + row0 * PWW;
        uint32_t* a1 = A + (row0 + 8) * PWW;
#pragma unroll
        for (int j = 0; j < 8; j++) {
            int col = n0w + 8 * j + 2 * tg;
            int wpos = n0w / 2 + 4 * j + tg;
            a0[wpos] = pack_bf16x2(acc[mt][j][0] + b2s[col], acc[mt][j][1] + b2s[col + 1]);
            a1[wpos] = pack_bf16x2(acc[mt][j][2] + b2s[col], acc[mt][j][3] + b2s[col + 1]);
        }
    }
    __syncthreads();

    // Row-coalesced scatter: 16 consecutive uint4 per live node row.
    for (int idx = tid; idx < 128 * 16; idx += 256) {
        int m = idx >> 4, q = idx & 15;
        if (!sdead[m])
            *(uint4*)(g_xbuf + (size_t)nodes[m] * 64 + q * 4) = *(const uint4*)(A + m * PWW + q * 4);
    }
}

// ---------------------------------------------------------------------------
// head: 128 rows/CTA, 256 threads, 2 CTAs/SM. gather (coalesced copy) ->
// 3x (GEMM+bias+ReLU) -> dot W4 + b4 -> sigmoid.
// ---------------------------------------------------------------------------
extern "C" __global__ void __launch_bounds__(256, 2)
head_kernel(const int* __restrict__ assoc,
            const float* __restrict__ b1g, const float* __restrict__ b2g,
            const float* __restrict__ b3g, const float* __restrict__ W4g,
            const float* __restrict__ b4g, float* __restrict__ out, int n)
{
    extern __shared__ uint32_t smw[];
    uint32_t* A = smw;
    uint32_t* B = smw + 128 * PWW;
    float* misc = (float*)(smw + 2 * 128 * PWW);
    // misc: [0]b1 [128]b2 [256]b3 [384]W4 [512]part(256) [768]nodes(int 128)
    float* W4s  = misc + 384;
    float* part = misc + 512;
    int*   nodes = (int*)(misc + 768);

    const int tid = threadIdx.x, lane = tid & 31, w = tid >> 5;
    const int m0 = blockIdx.x * 128;
    const int m0w = (w & 3) * 32, n0w = (w >> 2) * 64;
    const int g = lane >> 2, tg = lane & 3;
    const uint32_t Au = smem_u32(A), Bu = smem_u32(B);

    if (tid < 128) {
        misc[tid]       = b1g[tid];
        misc[128 + tid] = b2g[tid];
        misc[256 + tid] = b3g[tid];
        W4s[tid]        = W4g[tid];
        int r = m0 + tid;
        nodes[tid] = (r < n) ? assoc[r] : 0;
    }
    __syncthreads();

    // Gather -> A (natural layout, coalesced 256B per node row).
    for (int idx = tid; idx < 128 * 16; idx += 256) {
        int m = idx >> 4, q = idx & 15;
        uint4 v = *(const uint4*)(g_xbuf + (size_t)nodes[m] * 64 + q * 4);
        *(uint4*)(A + m * PWW + q * 4) = v;
    }
    stageB(B, g_wB[2], tid);
    __syncthreads();

#pragma unroll 1
    for (int lyr = 0; lyr < 3; lyr++) {
        float acc[2][8][4];
#pragma unroll
        for (int mt = 0; mt < 2; mt++)
#pragma unroll
            for (int nt = 0; nt < 8; nt++)
#pragma unroll
                for (int c = 0; c < 4; c++) acc[mt][nt][c] = 0.f;

        gemm_frag(Au, Bu, acc, lane, m0w, n0w);
        __syncthreads();   // all warps done reading A and B

        const float* bias = misc + lyr * 128;
        if (lyr < 2) {
            // relu + bias + pack -> A in place (natural layout), restage B.
#pragma unroll
            for (int mt = 0; mt < 2; mt++) {
                int row0 = m0w + 16 * mt + g;
                uint32_t* a0 = A + row0 * PWW;
                uint32_t* a1 = A + (row0 + 8) * PWW;
#pragma unroll
                for (int j = 0; j < 8; j++) {
                    int col = n0w + 8 * j + 2 * tg;
                    int wpos = n0w / 2 + 4 * j + tg;
                    a0[wpos] = pack_bf16x2(fmaxf(acc[mt][j][0] + bias[col], 0.f),
                                           fmaxf(acc[mt][j][1] + bias[col + 1], 0.f));
                    a1[wpos] = pack_bf16x2(fmaxf(acc[mt][j][2] + bias[col], 0.f),
                                           fmaxf(acc[mt][j][3] + bias[col + 1], 0.f));
                }
            }
            stageB(B, g_wB[3 + lyr], tid);
            __syncthreads();
        } else {
            // Final: relu + bias, dot with W4, reduce 4-lane group.
#pragma unroll
            for (int mt = 0; mt < 2; mt++) {
                float p0 = 0.f, p1 = 0.f;
#pragma unroll
                for (int j = 0; j < 8; j++) {
                    int col = n0w + 8 * j + 2 * tg;
                    p0 = fmaf(fmaxf(acc[mt][j][0] + bias[col], 0.f),     W4s[col],     p0);
                    p0 = fmaf(fmaxf(acc[mt][j][1] + bias[col + 1], 0.f), W4s[col + 1], p0);
                    p1 = fmaf(fmaxf(acc[mt][j][2] + bias[col], 0.f),     W4s[col],     p1);
                    p1 = fmaf(fmaxf(acc[mt][j][3] + bias[col + 1], 0.f), W4s[col + 1], p1);
                }
                p0 += __shfl_xor_sync(0xffffffffu, p0, 1);
                p0 += __shfl_xor_sync(0xffffffffu, p0, 2);
                p1 += __shfl_xor_sync(0xffffffffu, p1, 1);
                p1 += __shfl_xor_sync(0xffffffffu, p1, 2);
                if (tg == 0) {
                    int row0 = m0w + 16 * mt + g;
                    part[(w >> 2) * 128 + row0]     = p0;
                    part[(w >> 2) * 128 + row0 + 8] = p1;
                }
            }
            __syncthreads();
            if (tid < 128) {
                int row = m0 + tid;
                if (row < n) {
                    float s = part[tid] + part[128 + tid] + __ldg(&b4g[0]);
                    out[row] = 1.f / (1.f + expf(-s));
                }
            }
        }
    }
}

// ---------------------------------------------------------------------------
// Launch
// ---------------------------------------------------------------------------
extern "C" void kernel_launch(void* const* d_in, const int* in_sizes, int n_in,
                              void* d_out, int out_size)
{
    (void)n_in; (void)out_size;
    const float* varf      = (const float*)d_in[0];
    const float* conf      = (const float*)d_in[1];
    const int*   assoc_var = (const int*)d_in[3];
    const int*   assoc_con = (const int*)d_in[4];
    const float* vW1 = (const float*)d_in[5];
    const float* vb1 = (const float*)d_in[6];
    const float* vW2 = (const float*)d_in[7];
    const float* vb2 = (const float*)d_in[8];
    const float* cW1 = (const float*)d_in[9];
    const float* cb1 = (const float*)d_in[10];
    const float* cW2 = (const float*)d_in[11];
    const float* cb2 = (const float*)d_in[12];
    const float* W1  = (const float*)d_in[13];
    const float* b1  = (const float*)d_in[14];
    const float* W2  = (const float*)d_in[15];
    const float* b2  = (const float*)d_in[16];
    const float* W3  = (const float*)d_in[17];
    const float* b3  = (const float*)d_in[18];
    const float* W4  = (const float*)d_in[19];
    const float* b4  = (const float*)d_in[20];
    float* out = (float*)d_out;

    const int n_var = in_sizes[0] / 2;
    const int n_con = in_sizes[1] / 2;

    // A(128*68) + B(128*68) + misc ≈ 72.3 KB per CTA -> 2 CTAs/SM.
    const int smem_bytes = (2 * 128 * PWW + 1024) * 4 + 256;

    cudaFuncSetAttribute(mlp2_scatter_kernel,
                         cudaFuncAttributeMaxDynamicSharedMemorySize, smem_bytes);
    cudaFuncSetAttribute(head_kernel,
                         cudaFuncAttributeMaxDynamicSharedMemorySize, smem_bytes);

    unsigned char* mask_dev = nullptr;
    cudaGetSymbolAddress((void**)&mask_dev, g_mask);

    const int gv = (n_var + 127) / 128;
    const int gc = (n_con + 127) / 128;

    prep_kernel<<<(5 * 128 * 64 + 255) / 256, 256>>>(vW2, cW2, W1, W2, W3);
    mark_kernel<<<(n_con + 255) / 256, 256>>>(assoc_con, n_con);
    // var first (dead rows skipped), con second (overwrites), then head.
    mlp2_scatter_kernel<<<gv, 256, smem_bytes>>>(varf, assoc_var, vW1, vb1, vb2, mask_dev, n_var, 0);
    mlp2_scatter_kernel<<<gc, 256, smem_bytes>>>(conf, assoc_con, cW1, cb1, cb2, nullptr, n_con, 1);
    head_kernel<<<gv, 256, smem_bytes>>>(assoc_var, b1, b2, b3, W4, b4, out, n_var);
}

// round 11
// speedup vs baseline: 1.3278x; 1.3278x over previous
#include <cuda_runtime.h>
#include <cuda_bf16.h>
#include <math.h>
#include <stdint.h>

// ---------------------------------------------------------------------------
// Net_76690936037575 — R11: fully fused. winner[node] = last writer (var pass
// then con pass, matching reference overwrite order). One persistent-style
// fused kernel per 128-row tile: gather (feats, src flag) -> layer1 (fp32)
// -> mlp2-L2 GEMM (vW2/cW2 by tile homogeneity; per-row bias) -> 3 head
// GEMM+ReLU layers -> W4 dot + sigmoid. bf16 mma.sync m16n8k16, permuted-k
// SMEM word layout (R9, pitch 72 words = phase-perfect LDS.64).
// ---------------------------------------------------------------------------

#define PW 72   // words (bf16x2) per tile row: 64 data + 8 pad

// Transposed + permuted bf16x2 weights: 0=vW2^T 1=cW2^T 2=W1^T 3=W2^T 4=W3^T
__device__ uint32_t g_wB[5][128 * PW];
// winner[node] = source row, bit30 set if con.
__device__ int g_winner[1000000u];

__device__ __forceinline__ uint32_t pack_bf16x2(float lo, float hi) {
    uint32_t r;
    asm("cvt.rn.bf16x2.f32 %0, %1, %2;" : "=r"(r) : "f"(hi), "f"(lo));
    return r;
}

__device__ __forceinline__ void mma16(float* d, const uint32_t* a, const uint32_t* b) {
    asm volatile("mma.sync.aligned.m16n8k16.row.col.f32.bf16.bf16.f32 "
                 "{%0,%1,%2,%3}, {%4,%5,%6,%7}, {%8,%9}, {%0,%1,%2,%3};"
                 : "+f"(d[0]), "+f"(d[1]), "+f"(d[2]), "+f"(d[3])
                 : "r"(a[0]), "r"(a[1]), "r"(a[2]), "r"(a[3]),
                   "r"(b[0]), "r"(b[1]));
}

// Warp GEMM 32m x 64n x 128k over permuted bf16x2 word tiles (R9, proven).
__device__ __forceinline__ void gemm_frag(const uint32_t* __restrict__ As,
                                          const uint32_t* __restrict__ Bs,
                                          float acc[2][8][4],
                                          int lane, int m0w, int n0w)
{
    const int g = lane >> 2, tg = lane & 3;
    const uint32_t* Ab = As + (m0w + g) * PW + 2 * tg;
    const uint32_t* Bb = Bs + (n0w + g) * PW + 2 * tg;
#pragma unroll
    for (int kt = 0; kt < 8; kt++) {
        const int k0 = kt * 8;   // words
        uint2 a00 = *(const uint2*)(Ab + k0);
        uint2 a01 = *(const uint2*)(Ab + 8 * PW + k0);
        uint2 a10 = *(const uint2*)(Ab + 16 * PW + k0);
        uint2 a11 = *(const uint2*)(Ab + 24 * PW + k0);
        uint32_t a[2][4];
        a[0][0] = a00.x; a[0][1] = a01.x; a[0][2] = a00.y; a[0][3] = a01.y;
        a[1][0] = a10.x; a[1][1] = a11.x; a[1][2] = a10.y; a[1][3] = a11.y;
        uint32_t b[8][2];
#pragma unroll
        for (int nt = 0; nt < 8; nt++) {
            uint2 bv = *(const uint2*)(Bb + nt * 8 * PW + k0);
            b[nt][0] = bv.x; b[nt][1] = bv.y;
        }
#pragma unroll
        for (int mt = 0; mt < 2; mt++)
#pragma unroll
            for (int nt = 0; nt < 8; nt++)
                mma16(acc[mt][nt], a[mt], b[nt]);
    }
}

__device__ __forceinline__ void stageB(uint32_t* __restrict__ Bs,
                                       const uint32_t* __restrict__ wt, int tid)
{
    const uint4* src = (const uint4*)wt;
    uint4* dst = (uint4*)Bs;
#pragma unroll 3
    for (int i = tid; i < 128 * PW / 4; i += 256) dst[i] = src[i];
}

#define ZERO_ACC(acc)                                  \
    _Pragma("unroll") for (int mt = 0; mt < 2; mt++)   \
    _Pragma("unroll") for (int nt = 0; nt < 8; nt++)   \
    _Pragma("unroll") for (int c = 0; c < 4; c++) (acc)[mt][nt][c] = 0.f;

// ---------------------------------------------------------------------------
// Prep: g_wB[w][n*PW + (u&~7) + p(u&7)] = bf16x2(W[2u][n], W[2u+1][n]).
// ---------------------------------------------------------------------------
extern "C" __global__ void prep_kernel(const float* __restrict__ vW2, const float* __restrict__ cW2,
                                       const float* __restrict__ W1, const float* __restrict__ W2,
                                       const float* __restrict__ W3)
{
    int idx = blockIdx.x * 256 + threadIdx.x;
    if (idx >= 5 * 128 * 64) return;
    int w = idx >> 13, e = idx & 8191;
    int nn = e >> 6, u = e & 63;
    const float* src = (w == 0) ? vW2 : (w == 1) ? cW2 : (w == 2) ? W1 : (w == 3) ? W2 : W3;
    int uw = u & 7;
    int pos = (u & ~7) | ((uw & 3) << 1) | (uw >> 2);
    g_wB[w][nn * PW + pos] = pack_bf16x2(src[(2 * u) * 128 + nn], src[(2 * u + 1) * 128 + nn]);
}

// winner build: var pass first, con pass second (con overwrites).
extern "C" __global__ void winner_var_kernel(const int* __restrict__ av, int n)
{
    int i = blockIdx.x * 256 + threadIdx.x;
    if (i < n) g_winner[av[i]] = i;
}
extern "C" __global__ void winner_con_kernel(const int* __restrict__ ac, int n)
{
    int i = blockIdx.x * 256 + threadIdx.x;
    if (i < n) g_winner[ac[i]] = i | (1 << 30);
}

// ---------------------------------------------------------------------------
// Fused kernel: 128 rows/CTA, 256 threads, 2 CTAs/SM.
// ---------------------------------------------------------------------------
extern "C" __global__ void __launch_bounds__(256, 2)
fused_kernel(const float* __restrict__ varf, const float* __restrict__ conf,
             const int* __restrict__ assoc,
             const float* __restrict__ vW1, const float* __restrict__ vb1,
             const float* __restrict__ vb2,
             const float* __restrict__ cW1, const float* __restrict__ cb1,
             const float* __restrict__ cb2,
             const float* __restrict__ hb1, const float* __restrict__ hb2,
             const float* __restrict__ hb3,
             const float* __restrict__ W4g, const float* __restrict__ b4g,
             float* __restrict__ out, int n)
{
    extern __shared__ uint32_t smw[];
    uint32_t* A     = smw;                         // 128*PW words
    uint32_t* B     = smw + 128 * PW;              // 128*PW words
    uint32_t* stash = smw + 2 * 128 * PW;          // 128*64 words (mixed only)
    float* misc = (float*)(smw + 2 * 128 * PW + 128 * 64);
    // misc: [0]W1v(256) [256]W1c(256) [512]b1v [640]b1c [768]b2v [896]b2c
    //       [1024]hb1 [1152]hb2 [1280]hb3 [1408]W4 [1536]part(256)
    //       [1792]F0(128) [1920]F1(128) [2048]flags(int 128)
    float* W4s  = misc + 1408;
    float* part = misc + 1536;
    float* F0   = misc + 1792;
    float* F1   = misc + 1920;
    int* flags  = (int*)(misc + 2048);

    const int tid = threadIdx.x, lane = tid & 31, w = tid >> 5;
    const int m0 = blockIdx.x * 128;
    const int m0w = (w & 3) * 32, n0w = (w >> 2) * 64;
    const int g = lane >> 2, tg = lane & 3;

    if (tid < 256) { misc[tid] = vW1[tid]; misc[256 + tid] = cW1[tid]; }
    int myflag = 0;
    if (tid < 128) {
        misc[512 + tid]  = vb1[tid];
        misc[640 + tid]  = cb1[tid];
        misc[768 + tid]  = vb2[tid];
        misc[896 + tid]  = cb2[tid];
        misc[1024 + tid] = hb1[tid];
        misc[1152 + tid] = hb2[tid];
        misc[1280 + tid] = hb3[tid];
        W4s[tid]         = W4g[tid];
        int r = m0 + tid;
        float2 f = make_float2(0.f, 0.f);
        if (r < n) {
            int wv = g_winner[assoc[r]];
            myflag = (wv >> 30) & 1;
            int srow = wv & ((1 << 30) - 1);
            f = myflag ? ((const float2*)conf)[srow] : ((const float2*)varf)[srow];
        }
        flags[tid] = myflag;
        F0[tid] = f.x; F1[tid] = f.y;
    }
    int ncon = __syncthreads_count(myflag);
    int nvalid = n - m0; if (nvalid > 128) nvalid = 128;
    const bool allvar = (ncon == 0);
    const bool allcon = (ncon == nvalid);
    const bool mixed  = !allvar && !allcon;

    // Layer 1 (fp32, per-row weight set) -> A permuted bf16x2.
    for (int idx = tid; idx < 128 * 8; idx += 256) {
        int m = idx >> 3, c = idx & 7, k0 = c * 16;
        int fl = flags[m];
        const float* w1 = misc + fl * 256;
        const float* bb = misc + 512 + fl * 128;
        float f0 = F0[m], f1 = F1[m];
        uint32_t wv[8];
#pragma unroll
        for (int u = 0; u < 8; u++) {
            int k = k0 + 2 * u;
            float h0 = fmaxf(fmaf(f0, w1[k],     fmaf(f1, w1[128 + k],     bb[k])),     0.f);
            float h1 = fmaxf(fmaf(f0, w1[k + 1], fmaf(f1, w1[128 + k + 1], bb[k + 1])), 0.f);
            wv[u] = pack_bf16x2(h0, h1);
        }
        uint32_t* dst = A + m * PW + c * 8;
        *(uint4*)(dst)     = make_uint4(wv[0], wv[4], wv[1], wv[5]);
        *(uint4*)(dst + 4) = make_uint4(wv[2], wv[6], wv[3], wv[7]);
    }
    // Stage L2 weights: homogeneous picks the right one; mixed starts with vW2.
    stageB(B, g_wB[allcon ? 1 : 0], tid);
    __syncthreads();

    float acc[2][8][4];
    ZERO_ACC(acc);
    gemm_frag(A, B, acc, lane, m0w, n0w);
    __syncthreads();

    if (!mixed) {
        // Epilogue: +b2 (per-row source select), pack -> A in place.
#pragma unroll
        for (int mt = 0; mt < 2; mt++) {
            int row0 = m0w + 16 * mt + g;
            const float* b2_0 = misc + 768 + flags[row0] * 128;
            const float* b2_1 = misc + 768 + flags[row0 + 8] * 128;
            uint32_t* a0 = A + row0 * PW;
            uint32_t* a1 = A + (row0 + 8) * PW;
#pragma unroll
            for (int q = 0; q < 4; q++) {
                int colA = n0w + 16 * q + 2 * tg;
                int colB = colA + 8;
                int wpos = n0w / 2 + 8 * q + 2 * tg;
                uint2 p0, p1;
                p0.x = pack_bf16x2(acc[mt][2*q][0]   + b2_0[colA], acc[mt][2*q][1]   + b2_0[colA+1]);
                p0.y = pack_bf16x2(acc[mt][2*q+1][0] + b2_0[colB], acc[mt][2*q+1][1] + b2_0[colB+1]);
                p1.x = pack_bf16x2(acc[mt][2*q][2]   + b2_1[colA], acc[mt][2*q][3]   + b2_1[colA+1]);
                p1.y = pack_bf16x2(acc[mt][2*q+1][2] + b2_1[colB], acc[mt][2*q+1][3] + b2_1[colB+1]);
                *(uint2*)(a0 + wpos) = p0;
                *(uint2*)(a1 + wpos) = p1;
            }
        }
    } else {
        // Mixed tile: acc holds A@vW2. Save (+vb2) for ALL rows to stash,
        // then rerun with cW2 and merge per-row.
        const float* b2v = misc + 768;
        const float* b2c = misc + 896;
#pragma unroll
        for (int mt = 0; mt < 2; mt++) {
            int row0 = m0w + 16 * mt + g;
            uint32_t* s0 = stash + row0 * 64;
            uint32_t* s1 = stash + (row0 + 8) * 64;
#pragma unroll
            for (int q = 0; q < 4; q++) {
                int colA = n0w + 16 * q + 2 * tg;
                int colB = colA + 8;
                int wpos = n0w / 2 + 8 * q + 2 * tg;
                uint2 p0, p1;
                p0.x = pack_bf16x2(acc[mt][2*q][0]   + b2v[colA], acc[mt][2*q][1]   + b2v[colA+1]);
                p0.y = pack_bf16x2(acc[mt][2*q+1][0] + b2v[colB], acc[mt][2*q+1][1] + b2v[colB+1]);
                p1.x = pack_bf16x2(acc[mt][2*q][2]   + b2v[colA], acc[mt][2*q][3]   + b2v[colA+1]);
                p1.y = pack_bf16x2(acc[mt][2*q+1][2] + b2v[colB], acc[mt][2*q+1][3] + b2v[colB+1]);
                *(uint2*)(s0 + wpos) = p0;
                *(uint2*)(s1 + wpos) = p1;
            }
        }
        stageB(B, g_wB[1], tid);
        __syncthreads();
        ZERO_ACC(acc);
        gemm_frag(A, B, acc, lane, m0w, n0w);
        __syncthreads();
        // con rows from acc(+cb2) -> A
#pragma unroll
        for (int mt = 0; mt < 2; mt++) {
            int row0 = m0w + 16 * mt + g;
            bool c0 = flags[row0], c1 = flags[row0 + 8];
            uint32_t* a0 = A + row0 * PW;
            uint32_t* a1 = A + (row0 + 8) * PW;
#pragma unroll
            for (int q = 0; q < 4; q++) {
                int colA = n0w + 16 * q + 2 * tg;
                int colB = colA + 8;
                int wpos = n0w / 2 + 8 * q + 2 * tg;
                if (c0) {
                    uint2 p0;
                    p0.x = pack_bf16x2(acc[mt][2*q][0]   + b2c[colA], acc[mt][2*q][1]   + b2c[colA+1]);
                    p0.y = pack_bf16x2(acc[mt][2*q+1][0] + b2c[colB], acc[mt][2*q+1][1] + b2c[colB+1]);
                    *(uint2*)(a0 + wpos) = p0;
                }
                if (c1) {
                    uint2 p1;
                    p1.x = pack_bf16x2(acc[mt][2*q][2]   + b2c[colA], acc[mt][2*q][3]   + b2c[colA+1]);
                    p1.y = pack_bf16x2(acc[mt][2*q+1][2] + b2c[colB], acc[mt][2*q+1][3] + b2c[colB+1]);
                    *(uint2*)(a1 + wpos) = p1;
                }
            }
        }
        // var rows from stash -> A (disjoint rows; no barrier needed).
        for (int idx = tid; idx < 128 * 16; idx += 256) {
            int m = idx >> 4, q = idx & 15;
            if (!flags[m])
                *(uint4*)(A + m * PW + q * 4) = *(const uint4*)(stash + m * 64 + q * 4);
        }
    }
    stageB(B, g_wB[2], tid);
    __syncthreads();

    // 3 head layers.
#pragma unroll 1
    for (int lyr = 0; lyr < 3; lyr++) {
        ZERO_ACC(acc);
        gemm_frag(A, B, acc, lane, m0w, n0w);
        __syncthreads();

        const float* bias = misc + 1024 + lyr * 128;
        if (lyr < 2) {
#pragma unroll
            for (int mt = 0; mt < 2; mt++) {
                int row0 = m0w + 16 * mt + g;
                uint32_t* a0 = A + row0 * PW;
                uint32_t* a1 = A + (row0 + 8) * PW;
#pragma unroll
                for (int q = 0; q < 4; q++) {
                    int colA = n0w + 16 * q + 2 * tg;
                    int colB = colA + 8;
                    int wpos = n0w / 2 + 8 * q + 2 * tg;
                    uint2 p0, p1;
                    p0.x = pack_bf16x2(fmaxf(acc[mt][2*q][0]   + bias[colA], 0.f),
                                       fmaxf(acc[mt][2*q][1]   + bias[colA+1], 0.f));
                    p0.y = pack_bf16x2(fmaxf(acc[mt][2*q+1][0] + bias[colB], 0.f),
                                       fmaxf(acc[mt][2*q+1][1] + bias[colB+1], 0.f));
                    p1.x = pack_bf16x2(fmaxf(acc[mt][2*q][2]   + bias[colA], 0.f),
                                       fmaxf(acc[mt][2*q][3]   + bias[colA+1], 0.f));
                    p1.y = pack_bf16x2(fmaxf(acc[mt][2*q+1][2] + bias[colB], 0.f),
                                       fmaxf(acc[mt][2*q+1][3] + bias[colB+1], 0.f));
                    *(uint2*)(a0 + wpos) = p0;
                    *(uint2*)(a1 + wpos) = p1;
                }
            }
            stageB(B, g_wB[3 + lyr], tid);
            __syncthreads();
        } else {
            // Final: relu + bias, dot with W4, reduce 4-lane group.
#pragma unroll
            for (int mt = 0; mt < 2; mt++) {
                float p0 = 0.f, p1 = 0.f;
#pragma unroll
                for (int j = 0; j < 8; j++) {
                    int col = n0w + 8 * j + 2 * tg;
                    p0 = fmaf(fmaxf(acc[mt][j][0] + bias[col], 0.f),     W4s[col],     p0);
                    p0 = fmaf(fmaxf(acc[mt][j][1] + bias[col + 1], 0.f), W4s[col + 1], p0);
                    p1 = fmaf(fmaxf(acc[mt][j][2] + bias[col], 0.f),     W4s[col],     p1);
                    p1 = fmaf(fmaxf(acc[mt][j][3] + bias[col + 1], 0.f), W4s[col + 1], p1);
                }
                p0 += __shfl_xor_sync(0xffffffffu, p0, 1);
                p0 += __shfl_xor_sync(0xffffffffu, p0, 2);
                p1 += __shfl_xor_sync(0xffffffffu, p1, 1);
                p1 += __shfl_xor_sync(0xffffffffu, p1, 2);
                if (tg == 0) {
                    int row0 = m0w + 16 * mt + g;
                    part[(w >> 2) * 128 + row0]     = p0;
                    part[(w >> 2) * 128 + row0 + 8] = p1;
                }
            }
            __syncthreads();
            if (tid < 128) {
                int row = m0 + tid;
                if (row < n) {
                    float s = part[tid] + part[128 + tid] + __ldg(&b4g[0]);
                    out[row] = 1.f / (1.f + expf(-s));
                }
            }
        }
    }
}

// ---------------------------------------------------------------------------
// Launch
// ---------------------------------------------------------------------------
extern "C" void kernel_launch(void* const* d_in, const int* in_sizes, int n_in,
                              void* d_out, int out_size)
{
    (void)n_in; (void)out_size;
    const float* varf      = (const float*)d_in[0];
    const float* conf      = (const float*)d_in[1];
    const int*   assoc_var = (const int*)d_in[3];
    const int*   assoc_con = (const int*)d_in[4];
    const float* vW1 = (const float*)d_in[5];
    const float* vb1 = (const float*)d_in[6];
    const float* vW2 = (const float*)d_in[7];
    const float* vb2 = (const float*)d_in[8];
    const float* cW1 = (const float*)d_in[9];
    const float* cb1 = (const float*)d_in[10];
    const float* cW2 = (const float*)d_in[11];
    const float* cb2 = (const float*)d_in[12];
    const float* W1  = (const float*)d_in[13];
    const float* b1  = (const float*)d_in[14];
    const float* W2  = (const float*)d_in[15];
    const float* b2  = (const float*)d_in[16];
    const float* W3  = (const float*)d_in[17];
    const float* b3  = (const float*)d_in[18];
    const float* W4  = (const float*)d_in[19];
    const float* b4  = (const float*)d_in[20];
    float* out = (float*)d_out;

    const int n_var = in_sizes[0] / 2;
    const int n_con = in_sizes[1] / 2;

    // A(128*72) + B(128*72) + stash(128*64) + misc(2176 w) = 115200 B/CTA.
    const int smem_bytes = (2 * 128 * PW + 128 * 64 + 2176) * 4;

    cudaFuncSetAttribute(fused_kernel,
                         cudaFuncAttributeMaxDynamicSharedMemorySize, smem_bytes);

    const int gv = (n_var + 127) / 128;

    prep_kernel<<<(5 * 128 * 64 + 255) / 256, 256>>>(vW2, cW2, W1, W2, W3);
    winner_var_kernel<<<(n_var + 255) / 256, 256>>>(assoc_var, n_var);
    winner_con_kernel<<<(n_con + 255) / 256, 256>>>(assoc_con, n_con);
    fused_kernel<<<gv, 256, smem_bytes>>>(varf, conf, assoc_var,
                                          vW1, vb1, vb2, cW1, cb1, cb2,
                                          b1, b2, b3, W4, b4, out, n_var);
}

// round 12
// speedup vs baseline: 1.3722x; 1.0335x over previous
#include <cuda_runtime.h>
#include <cuda_bf16.h>
#include <math.h>
#include <stdint.h>

// ---------------------------------------------------------------------------
// Net_76690936037575 — R12: algebraic fusion. mlp2-L2 has no activation, so
// (h@W2 + b2)@W1 + b1 == h@(W2@W1) + (b2@W1 + b1). Precompute comb_{v,c} =
// {v,c}W2 @ W1 (fp32, one bf16 rounding) and bias_{v,c} = {v,c}b2@W1 + b1.
// Fused kernel per 128-row tile: gather feats via winner[] -> layer1 (fp32)
// -> GEMM comb (+bias, ReLU) -> GEMM W2h (+b2h, ReLU) -> GEMM W3h (+b3h,
// ReLU, W4-dot, sigmoid). 3 GEMMs/tile instead of 4.
// bf16 mma.sync m16n8k16, permuted-k SMEM word layout (pitch 72 words).
// ---------------------------------------------------------------------------

#define PW 72   // words (bf16x2) per tile row: 64 data + 8 pad

// Transposed + permuted bf16x2 weights: 0=comb_v^T 1=comb_c^T 2=W2h^T 3=W3h^T
__device__ uint32_t g_wB[4][128 * PW];
// Combined biases: [0]=vb2@W1+b1, [1]=cb2@W1+b1
__device__ float g_biasComb[2][128];
// winner[node] = source row, bit30 set if con.
__device__ int g_winner[1000000u];

__device__ __forceinline__ uint32_t pack_bf16x2(float lo, float hi) {
    uint32_t r;
    asm("cvt.rn.bf16x2.f32 %0, %1, %2;" : "=r"(r) : "f"(hi), "f"(lo));
    return r;
}

__device__ __forceinline__ void mma16(float* d, const uint32_t* a, const uint32_t* b) {
    asm volatile("mma.sync.aligned.m16n8k16.row.col.f32.bf16.bf16.f32 "
                 "{%0,%1,%2,%3}, {%4,%5,%6,%7}, {%8,%9}, {%0,%1,%2,%3};"
                 : "+f"(d[0]), "+f"(d[1]), "+f"(d[2]), "+f"(d[3])
                 : "r"(a[0]), "r"(a[1]), "r"(a[2]), "r"(a[3]),
                   "r"(b[0]), "r"(b[1]));
}

// Warp GEMM 32m x 64n x 128k over permuted bf16x2 word tiles (R9, proven).
__device__ __forceinline__ void gemm_frag(const uint32_t* __restrict__ As,
                                          const uint32_t* __restrict__ Bs,
                                          float acc[2][8][4],
                                          int lane, int m0w, int n0w)
{
    const int g = lane >> 2, tg = lane & 3;
    const uint32_t* Ab = As + (m0w + g) * PW + 2 * tg;
    const uint32_t* Bb = Bs + (n0w + g) * PW + 2 * tg;
#pragma unroll
    for (int kt = 0; kt < 8; kt++) {
        const int k0 = kt * 8;   // words
        uint2 a00 = *(const uint2*)(Ab + k0);
        uint2 a01 = *(const uint2*)(Ab + 8 * PW + k0);
        uint2 a10 = *(const uint2*)(Ab + 16 * PW + k0);
        uint2 a11 = *(const uint2*)(Ab + 24 * PW + k0);
        uint32_t a[2][4];
        a[0][0] = a00.x; a[0][1] = a01.x; a[0][2] = a00.y; a[0][3] = a01.y;
        a[1][0] = a10.x; a[1][1] = a11.x; a[1][2] = a10.y; a[1][3] = a11.y;
        uint32_t b[8][2];
#pragma unroll
        for (int nt = 0; nt < 8; nt++) {
            uint2 bv = *(const uint2*)(Bb + nt * 8 * PW + k0);
            b[nt][0] = bv.x; b[nt][1] = bv.y;
        }
#pragma unroll
        for (int mt = 0; mt < 2; mt++)
#pragma unroll
            for (int nt = 0; nt < 8; nt++)
                mma16(acc[mt][nt], a[mt], b[nt]);
    }
}

__device__ __forceinline__ void stageB(uint32_t* __restrict__ Bs,
                                       const uint32_t* __restrict__ wt, int tid)
{
    const uint4* src = (const uint4*)wt;
    uint4* dst = (uint4*)Bs;
#pragma unroll 3
    for (int i = tid; i < 128 * PW / 4; i += 256) dst[i] = src[i];
}

#define ZERO_ACC(acc)                                  \
    _Pragma("unroll") for (int mt = 0; mt < 2; mt++)   \
    _Pragma("unroll") for (int nt = 0; nt < 8; nt++)   \
    _Pragma("unroll") for (int c = 0; c < 4; c++) (acc)[mt][nt][c] = 0.f;

// ---------------------------------------------------------------------------
// prep_trans: slots 2,3 = W2h^T, W3h^T (permuted bf16x2).
// ---------------------------------------------------------------------------
extern "C" __global__ void prep_trans(const float* __restrict__ W2h,
                                      const float* __restrict__ W3h)
{
    int idx = blockIdx.x * 256 + threadIdx.x;
    if (idx >= 2 * 8192) return;
    int w = idx >> 13, e = idx & 8191;
    int nn = e >> 6, u = e & 63;
    const float* src = w ? W3h : W2h;
    int uw = u & 7;
    int pos = (u & ~7) | ((uw & 3) << 1) | (uw >> 2);
    g_wB[2 + w][nn * PW + pos] = pack_bf16x2(src[(2 * u) * 128 + nn], src[(2 * u + 1) * 128 + nn]);
}

// prep_comb: slots 0,1 = ({v,c}W2 @ W1h)^T (fp32 product, one bf16 rounding).
extern "C" __global__ void prep_comb(const float* __restrict__ vW2,
                                     const float* __restrict__ cW2,
                                     const float* __restrict__ W1h)
{
    int idx = blockIdx.x * 256 + threadIdx.x;
    if (idx >= 2 * 8192) return;
    int w = idx >> 13, e = idx & 8191;
    int nn = e >> 6, u = e & 63;
    const float* src = w ? cW2 : vW2;
    const float* r0 = src + (2 * u) * 128;
    const float* r1 = r0 + 128;
    float d0 = 0.f, d1 = 0.f;
#pragma unroll 4
    for (int j = 0; j < 128; j++) {
        float wj = __ldg(&W1h[j * 128 + nn]);
        d0 = fmaf(r0[j], wj, d0);
        d1 = fmaf(r1[j], wj, d1);
    }
    int uw = u & 7;
    int pos = (u & ~7) | ((uw & 3) << 1) | (uw >> 2);
    g_wB[w][nn * PW + pos] = pack_bf16x2(d0, d1);
}

// prep_bias: g_biasComb[{v,c}][n] = {v,c}b2 @ W1h + hb1.
extern "C" __global__ void prep_bias(const float* __restrict__ vb2,
                                     const float* __restrict__ cb2,
                                     const float* __restrict__ W1h,
                                     const float* __restrict__ hb1)
{
    int tid = threadIdx.x;           // 256
    int w = tid >> 7, nn = tid & 127;
    const float* b = w ? cb2 : vb2;
    float s = hb1[nn];
#pragma unroll 4
    for (int j = 0; j < 128; j++) s = fmaf(b[j], W1h[j * 128 + nn], s);
    g_biasComb[w][nn] = s;
}

// winner build: var pass first, con pass second (con overwrites).
extern "C" __global__ void winner_var_kernel(const int* __restrict__ av, int n)
{
    int i = blockIdx.x * 256 + threadIdx.x;
    if (i < n) g_winner[av[i]] = i;
}
extern "C" __global__ void winner_con_kernel(const int* __restrict__ ac, int n)
{
    int i = blockIdx.x * 256 + threadIdx.x;
    if (i < n) g_winner[ac[i]] = i | (1 << 30);
}

// ---------------------------------------------------------------------------
// Fused kernel: 128 rows/CTA, 256 threads, 2 CTAs/SM. 3 GEMMs per tile.
// ---------------------------------------------------------------------------
extern "C" __global__ void __launch_bounds__(256, 2)
fused_kernel(const float* __restrict__ varf, const float* __restrict__ conf,
             const int* __restrict__ assoc,
             const float* __restrict__ vW1, const float* __restrict__ vb1,
             const float* __restrict__ cW1, const float* __restrict__ cb1,
             const float* __restrict__ hb2, const float* __restrict__ hb3,
             const float* __restrict__ W4g, const float* __restrict__ b4g,
             float* __restrict__ out, int n)
{
    extern __shared__ uint32_t smw[];
    uint32_t* A     = smw;                         // 128*PW words
    uint32_t* B     = smw + 128 * PW;              // 128*PW words
    uint32_t* stash = smw + 2 * 128 * PW;          // 128*64 words (mixed only)
    float* misc = (float*)(smw + 2 * 128 * PW + 128 * 64);
    // misc: [0]W1v(256) [256]W1c(256) [512]b1v [640]b1c [768]biasv [896]biasc
    //       [1024]hb2 [1152]hb3 [1280]W4 [1408]part(256) [1664]F0 [1792]F1
    //       [1920]flags(int 128)   total 2048 words
    float* W4s  = misc + 1280;
    float* part = misc + 1408;
    float* F0   = misc + 1664;
    float* F1   = misc + 1792;
    int* flags  = (int*)(misc + 1920);

    const int tid = threadIdx.x, lane = tid & 31, w = tid >> 5;
    const int m0 = blockIdx.x * 128;
    const int m0w = (w & 3) * 32, n0w = (w >> 2) * 64;
    const int g = lane >> 2, tg = lane & 3;

    if (tid < 256) { misc[tid] = vW1[tid]; misc[256 + tid] = cW1[tid]; }
    int myflag = 0;
    if (tid < 128) {
        misc[512 + tid]  = vb1[tid];
        misc[640 + tid]  = cb1[tid];
        misc[768 + tid]  = g_biasComb[0][tid];
        misc[896 + tid]  = g_biasComb[1][tid];
        misc[1024 + tid] = hb2[tid];
        misc[1152 + tid] = hb3[tid];
        W4s[tid]         = W4g[tid];
        int r = m0 + tid;
        float2 f = make_float2(0.f, 0.f);
        if (r < n) {
            int wv = g_winner[assoc[r]];
            myflag = (wv >> 30) & 1;
            int srow = wv & ((1 << 30) - 1);
            f = myflag ? ((const float2*)conf)[srow] : ((const float2*)varf)[srow];
        }
        flags[tid] = myflag;
        F0[tid] = f.x; F1[tid] = f.y;
    }
    int ncon = __syncthreads_count(myflag);
    int nvalid = n - m0; if (nvalid > 128) nvalid = 128;
    const bool allcon = (ncon == nvalid);
    const bool mixed  = (ncon != 0) && !allcon;

    // Layer 1 (fp32, per-row weight set) -> A permuted bf16x2.
    for (int idx = tid; idx < 128 * 8; idx += 256) {
        int m = idx >> 3, c = idx & 7, k0 = c * 16;
        int fl = flags[m];
        const float* w1 = misc + fl * 256;
        const float* bb = misc + 512 + fl * 128;
        float f0 = F0[m], f1 = F1[m];
        uint32_t wv[8];
#pragma unroll
        for (int u = 0; u < 8; u++) {
            int k = k0 + 2 * u;
            float h0 = fmaxf(fmaf(f0, w1[k],     fmaf(f1, w1[128 + k],     bb[k])),     0.f);
            float h1 = fmaxf(fmaf(f0, w1[k + 1], fmaf(f1, w1[128 + k + 1], bb[k + 1])), 0.f);
            wv[u] = pack_bf16x2(h0, h1);
        }
        uint32_t* dst = A + m * PW + c * 8;
        *(uint4*)(dst)     = make_uint4(wv[0], wv[4], wv[1], wv[5]);
        *(uint4*)(dst + 4) = make_uint4(wv[2], wv[6], wv[3], wv[7]);
    }
    // Stage comb weights: homogeneous picks right one; mixed starts with comb_v.
    stageB(B, g_wB[allcon ? 1 : 0], tid);
    __syncthreads();

    float acc[2][8][4];
    ZERO_ACC(acc);
    gemm_frag(A, B, acc, lane, m0w, n0w);
    __syncthreads();

    if (!mixed) {
        // Epilogue: relu(acc + bias_sel[row]) -> A in place.
#pragma unroll
        for (int mt = 0; mt < 2; mt++) {
            int row0 = m0w + 16 * mt + g;
            const float* b0 = misc + 768 + flags[row0] * 128;
            const float* b1r = misc + 768 + flags[row0 + 8] * 128;
            uint32_t* a0 = A + row0 * PW;
            uint32_t* a1 = A + (row0 + 8) * PW;
#pragma unroll
            for (int q = 0; q < 4; q++) {
                int colA = n0w + 16 * q + 2 * tg;
                int colB = colA + 8;
                int wpos = n0w / 2 + 8 * q + 2 * tg;
                uint2 p0, p1;
                p0.x = pack_bf16x2(fmaxf(acc[mt][2*q][0]   + b0[colA], 0.f),
                                   fmaxf(acc[mt][2*q][1]   + b0[colA+1], 0.f));
                p0.y = pack_bf16x2(fmaxf(acc[mt][2*q+1][0] + b0[colB], 0.f),
                                   fmaxf(acc[mt][2*q+1][1] + b0[colB+1], 0.f));
                p1.x = pack_bf16x2(fmaxf(acc[mt][2*q][2]   + b1r[colA], 0.f),
                                   fmaxf(acc[mt][2*q][3]   + b1r[colA+1], 0.f));
                p1.y = pack_bf16x2(fmaxf(acc[mt][2*q+1][2] + b1r[colB], 0.f),
                                   fmaxf(acc[mt][2*q+1][3] + b1r[colB+1], 0.f));
                *(uint2*)(a0 + wpos) = p0;
                *(uint2*)(a1 + wpos) = p1;
            }
        }
    } else {
        // Mixed: stash relu(acc + biasv) for ALL rows, rerun with comb_c, merge.
        const float* bv = misc + 768;
        const float* bc = misc + 896;
#pragma unroll
        for (int mt = 0; mt < 2; mt++) {
            int row0 = m0w + 16 * mt + g;
            uint32_t* s0 = stash + row0 * 64;
            uint32_t* s1 = stash + (row0 + 8) * 64;
#pragma unroll
            for (int q = 0; q < 4; q++) {
                int colA = n0w + 16 * q + 2 * tg;
                int colB = colA + 8;
                int wpos = n0w / 2 + 8 * q + 2 * tg;
                uint2 p0, p1;
                p0.x = pack_bf16x2(fmaxf(acc[mt][2*q][0]   + bv[colA], 0.f),
                                   fmaxf(acc[mt][2*q][1]   + bv[colA+1], 0.f));
                p0.y = pack_bf16x2(fmaxf(acc[mt][2*q+1][0] + bv[colB], 0.f),
                                   fmaxf(acc[mt][2*q+1][1] + bv[colB+1], 0.f));
                p1.x = pack_bf16x2(fmaxf(acc[mt][2*q][2]   + bv[colA], 0.f),
                                   fmaxf(acc[mt][2*q][3]   + bv[colA+1], 0.f));
                p1.y = pack_bf16x2(fmaxf(acc[mt][2*q+1][2] + bv[colB], 0.f),
                                   fmaxf(acc[mt][2*q+1][3] + bv[colB+1], 0.f));
                *(uint2*)(s0 + wpos) = p0;
                *(uint2*)(s1 + wpos) = p1;
            }
        }
        stageB(B, g_wB[1], tid);
        __syncthreads();
        ZERO_ACC(acc);
        gemm_frag(A, B, acc, lane, m0w, n0w);
        __syncthreads();
#pragma unroll
        for (int mt = 0; mt < 2; mt++) {
            int row0 = m0w + 16 * mt + g;
            bool c0 = flags[row0], c1 = flags[row0 + 8];
            uint32_t* a0 = A + row0 * PW;
            uint32_t* a1 = A + (row0 + 8) * PW;
#pragma unroll
            for (int q = 0; q < 4; q++) {
                int colA = n0w + 16 * q + 2 * tg;
                int colB = colA + 8;
                int wpos = n0w / 2 + 8 * q + 2 * tg;
                if (c0) {
                    uint2 p0;
                    p0.x = pack_bf16x2(fmaxf(acc[mt][2*q][0]   + bc[colA], 0.f),
                                       fmaxf(acc[mt][2*q][1]   + bc[colA+1], 0.f));
                    p0.y = pack_bf16x2(fmaxf(acc[mt][2*q+1][0] + bc[colB], 0.f),
                                       fmaxf(acc[mt][2*q+1][1] + bc[colB+1], 0.f));
                    *(uint2*)(a0 + wpos) = p0;
                }
                if (c1) {
                    uint2 p1;
                    p1.x = pack_bf16x2(fmaxf(acc[mt][2*q][2]   + bc[colA], 0.f),
                                       fmaxf(acc[mt][2*q][3]   + bc[colA+1], 0.f));
                    p1.y = pack_bf16x2(fmaxf(acc[mt][2*q+1][2] + bc[colB], 0.f),
                                       fmaxf(acc[mt][2*q+1][3] + bc[colB+1], 0.f));
                    *(uint2*)(a1 + wpos) = p1;
                }
            }
        }
        for (int idx = tid; idx < 128 * 16; idx += 256) {
            int m = idx >> 4, q = idx & 15;
            if (!flags[m])
                *(uint4*)(A + m * PW + q * 4) = *(const uint4*)(stash + m * 64 + q * 4);
        }
    }
    stageB(B, g_wB[2], tid);
    __syncthreads();

    // 2 head layers (W2h, W3h).
#pragma unroll 1
    for (int lyr = 0; lyr < 2; lyr++) {
        ZERO_ACC(acc);
        gemm_frag(A, B, acc, lane, m0w, n0w);
        __syncthreads();

        const float* bias = misc + 1024 + lyr * 128;
        if (lyr == 0) {
#pragma unroll
            for (int mt = 0; mt < 2; mt++) {
                int row0 = m0w + 16 * mt + g;
                uint32_t* a0 = A + row0 * PW;
                uint32_t* a1 = A + (row0 + 8) * PW;
#pragma unroll
                for (int q = 0; q < 4; q++) {
                    int colA = n0w + 16 * q + 2 * tg;
                    int colB = colA + 8;
                    int wpos = n0w / 2 + 8 * q + 2 * tg;
                    uint2 p0, p1;
                    p0.x = pack_bf16x2(fmaxf(acc[mt][2*q][0]   + bias[colA], 0.f),
                                       fmaxf(acc[mt][2*q][1]   + bias[colA+1], 0.f));
                    p0.y = pack_bf16x2(fmaxf(acc[mt][2*q+1][0] + bias[colB], 0.f),
                                       fmaxf(acc[mt][2*q+1][1] + bias[colB+1], 0.f));
                    p1.x = pack_bf16x2(fmaxf(acc[mt][2*q][2]   + bias[colA], 0.f),
                                       fmaxf(acc[mt][2*q][3]   + bias[colA+1], 0.f));
                    p1.y = pack_bf16x2(fmaxf(acc[mt][2*q+1][2] + bias[colB], 0.f),
                                       fmaxf(acc[mt][2*q+1][3] + bias[colB+1], 0.f));
                    *(uint2*)(a0 + wpos) = p0;
                    *(uint2*)(a1 + wpos) = p1;
                }
            }
            stageB(B, g_wB[3], tid);
            __syncthreads();
        } else {
            // Final: relu + bias, dot with W4, reduce 4-lane group.
#pragma unroll
            for (int mt = 0; mt < 2; mt++) {
                float p0 = 0.f, p1 = 0.f;
#pragma unroll
                for (int j = 0; j < 8; j++) {
                    int col = n0w + 8 * j + 2 * tg;
                    p0 = fmaf(fmaxf(acc[mt][j][0] + bias[col], 0.f),     W4s[col],     p0);
                    p0 = fmaf(fmaxf(acc[mt][j][1] + bias[col + 1], 0.f), W4s[col + 1], p0);
                    p1 = fmaf(fmaxf(acc[mt][j][2] + bias[col], 0.f),     W4s[col],     p1);
                    p1 = fmaf(fmaxf(acc[mt][j][3] + bias[col + 1], 0.f), W4s[col + 1], p1);
                }
                p0 += __shfl_xor_sync(0xffffffffu, p0, 1);
                p0 += __shfl_xor_sync(0xffffffffu, p0, 2);
                p1 += __shfl_xor_sync(0xffffffffu, p1, 1);
                p1 += __shfl_xor_sync(0xffffffffu, p1, 2);
                if (tg == 0) {
                    int row0 = m0w + 16 * mt + g;
                    part[(w >> 2) * 128 + row0]     = p0;
                    part[(w >> 2) * 128 + row0 + 8] = p1;
                }
            }
            __syncthreads();
            if (tid < 128) {
                int row = m0 + tid;
                if (row < n) {
                    float s = part[tid] + part[128 + tid] + __ldg(&b4g[0]);
                    out[row] = 1.f / (1.f + expf(-s));
                }
            }
        }
    }
}

// ---------------------------------------------------------------------------
// Launch
// ---------------------------------------------------------------------------
extern "C" void kernel_launch(void* const* d_in, const int* in_sizes, int n_in,
                              void* d_out, int out_size)
{
    (void)n_in; (void)out_size;
    const float* varf      = (const float*)d_in[0];
    const float* conf      = (const float*)d_in[1];
    const int*   assoc_var = (const int*)d_in[3];
    const int*   assoc_con = (const int*)d_in[4];
    const float* vW1 = (const float*)d_in[5];
    const float* vb1 = (const float*)d_in[6];
    const float* vW2 = (const float*)d_in[7];
    const float* vb2 = (const float*)d_in[8];
    const float* cW1 = (const float*)d_in[9];
    const float* cb1 = (const float*)d_in[10];
    const float* cW2 = (const float*)d_in[11];
    const float* cb2 = (const float*)d_in[12];
    const float* W1  = (const float*)d_in[13];
    const float* b1  = (const float*)d_in[14];
    const float* W2  = (const float*)d_in[15];
    const float* b2  = (const float*)d_in[16];
    const float* W3  = (const float*)d_in[17];
    const float* b3  = (const float*)d_in[18];
    const float* W4  = (const float*)d_in[19];
    const float* b4  = (const float*)d_in[20];
    float* out = (float*)d_out;

    const int n_var = in_sizes[0] / 2;
    const int n_con = in_sizes[1] / 2;

    // A(128*72) + B(128*72) + stash(128*64) + misc(2048 w) = 114688 B/CTA.
    const int smem_bytes = (2 * 128 * PW + 128 * 64 + 2048) * 4;

    cudaFuncSetAttribute(fused_kernel,
                         cudaFuncAttributeMaxDynamicSharedMemorySize, smem_bytes);

    const int gv = (n_var + 127) / 128;

    prep_trans<<<64, 256>>>(W2, W3);
    prep_comb<<<64, 256>>>(vW2, cW2, W1);
    prep_bias<<<1, 256>>>(vb2, cb2, W1, b1);
    winner_var_kernel<<<(n_var + 255) / 256, 256>>>(assoc_var, n_var);
    winner_con_kernel<<<(n_con + 255) / 256, 256>>>(assoc_con, n_con);
    fused_kernel<<<gv, 256, smem_bytes>>>(varf, conf, assoc_var,
                                          vW1, vb1, cW1, cb1,
                                          b2, b3, W4, b4, out, n_var);
}

// round 13
// speedup vs baseline: 1.5085x; 1.0993x over previous
#include <cuda_runtime.h>
#include <cuda_bf16.h>
#include <math.h>
#include <stdint.h>

// ---------------------------------------------------------------------------
// Net_76690936037575 — R13: class-compacted homogeneous tiles + cp.async
// double-buffered weight staging.
//   comb_{v,c} = {v,c}W2 @ W1h (fp32 product, one bf16 rounding)
//   bias_{v,c} = {v,c}b2 @ W1h + hb1
// Rows are compacted into var-winner / con-winner lists (block-aggregated
// atomics); every fused tile is homogeneous. Per tile: layer1 (fp32) -> A;
// GEMM comb (+biasC, ReLU); GEMM W2h (+hb2, ReLU); GEMM W3h (+hb3, ReLU,
// W4-dot, sigmoid) -> scattered 4B store to out[row].
// bf16 mma.sync m16n8k16, permuted-k SMEM word layout (pitch 72 words).
// ---------------------------------------------------------------------------

#define PW 72   // words (bf16x2) per tile row: 64 data + 8 pad
#define TILE_WORDS (128 * PW)   // 9216 words = 36864 B

// Transposed + permuted bf16x2 weights: 0=comb_v^T 1=comb_c^T 2=W2h^T 3=W3h^T
__device__ uint32_t g_wB[4][TILE_WORDS];
// Combined biases: [0]=vb2@W1+b1, [1]=cb2@W1+b1
__device__ float g_biasComb[2][128];
// winner[node] = source row, bit30 set if con.
__device__ int g_winner[1000000u];
// class-compacted output-row lists + counters
__device__ int g_listv[1000000u];
__device__ int g_listc[1000000u];
__device__ int g_cnt[2];

__device__ __forceinline__ uint32_t smem_u32(const void* p) {
    uint32_t a;
    asm("{ .reg .u64 t; cvta.to.shared.u64 t, %1; cvt.u32.u64 %0, t; }" : "=r"(a) : "l"(p));
    return a;
}
__device__ __forceinline__ uint32_t pack_bf16x2(float lo, float hi) {
    uint32_t r;
    asm("cvt.rn.bf16x2.f32 %0, %1, %2;" : "=r"(r) : "f"(hi), "f"(lo));
    return r;
}
__device__ __forceinline__ void mma16(float* d, const uint32_t* a, const uint32_t* b) {
    asm volatile("mma.sync.aligned.m16n8k16.row.col.f32.bf16.bf16.f32 "
                 "{%0,%1,%2,%3}, {%4,%5,%6,%7}, {%8,%9}, {%0,%1,%2,%3};"
                 : "+f"(d[0]), "+f"(d[1]), "+f"(d[2]), "+f"(d[3])
                 : "r"(a[0]), "r"(a[1]), "r"(a[2]), "r"(a[3]),
                   "r"(b[0]), "r"(b[1]));
}

// Warp GEMM 32m x 64n x 128k over permuted bf16x2 word tiles (R9, proven).
__device__ __forceinline__ void gemm_frag(const uint32_t* __restrict__ As,
                                          const uint32_t* __restrict__ Bs,
                                          float acc[2][8][4],
                                          int lane, int m0w, int n0w)
{
    const int g = lane >> 2, tg = lane & 3;
    const uint32_t* Ab = As + (m0w + g) * PW + 2 * tg;
    const uint32_t* Bb = Bs + (n0w + g) * PW + 2 * tg;
#pragma unroll
    for (int kt = 0; kt < 8; kt++) {
        const int k0 = kt * 8;   // words
        uint2 a00 = *(const uint2*)(Ab + k0);
        uint2 a01 = *(const uint2*)(Ab + 8 * PW + k0);
        uint2 a10 = *(const uint2*)(Ab + 16 * PW + k0);
        uint2 a11 = *(const uint2*)(Ab + 24 * PW + k0);
        uint32_t a[2][4];
        a[0][0] = a00.x; a[0][1] = a01.x; a[0][2] = a00.y; a[0][3] = a01.y;
        a[1][0] = a10.x; a[1][1] = a11.x; a[1][2] = a10.y; a[1][3] = a11.y;
        uint32_t b[8][2];
#pragma unroll
        for (int nt = 0; nt < 8; nt++) {
            uint2 bv = *(const uint2*)(Bb + nt * 8 * PW + k0);
            b[nt][0] = bv.x; b[nt][1] = bv.y;
        }
#pragma unroll
        for (int mt = 0; mt < 2; mt++)
#pragma unroll
            for (int nt = 0; nt < 8; nt++)
                mma16(acc[mt][nt], a[mt], b[nt]);
    }
}

// Async weight staging: 2304 x 16B via cp.async (9 per thread), one group.
__device__ __forceinline__ void stage_async(uint32_t Bu, const uint32_t* wt, int tid)
{
    const char* src = (const char*)wt;
#pragma unroll
    for (int i = 0; i < 9; i++) {
        int idx = tid + i * 256;   // < 2304
        asm volatile("cp.async.cg.shared.global [%0], [%1], 16;"
                     :: "r"(Bu + idx * 16), "l"(src + idx * 16) : "memory");
    }
    asm volatile("cp.async.commit_group;" ::: "memory");
}
#define CP_WAIT_ALL() asm volatile("cp.async.wait_group 0;" ::: "memory")

#define ZERO_ACC(acc)                                  \
    _Pragma("unroll") for (int mt = 0; mt < 2; mt++)   \
    _Pragma("unroll") for (int nt = 0; nt < 8; nt++)   \
    _Pragma("unroll") for (int c = 0; c < 4; c++) (acc)[mt][nt][c] = 0.f;

// ---------------------------------------------------------------------------
// prep kernels
// ---------------------------------------------------------------------------
extern "C" __global__ void prep_trans(const float* __restrict__ W2h,
                                      const float* __restrict__ W3h)
{
    int idx = blockIdx.x * 256 + threadIdx.x;
    if (idx >= 2 * 8192) return;
    int w = idx >> 13, e = idx & 8191;
    int nn = e >> 6, u = e & 63;
    const float* src = w ? W3h : W2h;
    int uw = u & 7;
    int pos = (u & ~7) | ((uw & 3) << 1) | (uw >> 2);
    g_wB[2 + w][nn * PW + pos] = pack_bf16x2(src[(2 * u) * 128 + nn], src[(2 * u + 1) * 128 + nn]);
}

extern "C" __global__ void prep_comb(const float* __restrict__ vW2,
                                     const float* __restrict__ cW2,
                                     const float* __restrict__ W1h)
{
    int idx = blockIdx.x * 256 + threadIdx.x;
    if (idx >= 2 * 8192) return;
    int w = idx >> 13, e = idx & 8191;
    int nn = e >> 6, u = e & 63;
    const float* src = w ? cW2 : vW2;
    const float* r0 = src + (2 * u) * 128;
    const float* r1 = r0 + 128;
    float d0 = 0.f, d1 = 0.f;
#pragma unroll 4
    for (int j = 0; j < 128; j++) {
        float wj = __ldg(&W1h[j * 128 + nn]);
        d0 = fmaf(r0[j], wj, d0);
        d1 = fmaf(r1[j], wj, d1);
    }
    int uw = u & 7;
    int pos = (u & ~7) | ((uw & 3) << 1) | (uw >> 2);
    g_wB[w][nn * PW + pos] = pack_bf16x2(d0, d1);
}

extern "C" __global__ void prep_bias(const float* __restrict__ vb2,
                                     const float* __restrict__ cb2,
                                     const float* __restrict__ W1h,
                                     const float* __restrict__ hb1)
{
    int tid = threadIdx.x;           // 256
    int w = tid >> 7, nn = tid & 127;
    const float* b = w ? cb2 : vb2;
    float s = hb1[nn];
#pragma unroll 4
    for (int j = 0; j < 128; j++) s = fmaf(b[j], W1h[j * 128 + nn], s);
    g_biasComb[w][nn] = s;
}

extern "C" __global__ void reset_kernel()
{
    if (threadIdx.x < 2) g_cnt[threadIdx.x] = 0;
}

// winner build: var pass first, con pass second (con overwrites).
extern "C" __global__ void winner_var_kernel(const int* __restrict__ av, int n)
{
    int i = blockIdx.x * 256 + threadIdx.x;
    if (i < n) g_winner[av[i]] = i;
}
extern "C" __global__ void winner_con_kernel(const int* __restrict__ ac, int n)
{
    int i = blockIdx.x * 256 + threadIdx.x;
    if (i < n) g_winner[ac[i]] = i | (1 << 30);
}

// Block-aggregated class compaction of output rows.
extern "C" __global__ void compact_kernel(const int* __restrict__ av, int n)
{
    __shared__ int warpCnt[8][2];
    __shared__ int baseS[2];
    int i = blockIdx.x * 256 + threadIdx.x;
    int lane = threadIdx.x & 31, wid = threadIdx.x >> 5;
    int valid = (i < n);
    int flag = 0;
    if (valid) flag = (g_winner[av[i]] >> 30) & 1;
    unsigned m1 = __ballot_sync(0xffffffffu, valid && flag);
    unsigned m0 = __ballot_sync(0xffffffffu, valid && !flag);
    if (lane == 0) { warpCnt[wid][0] = __popc(m0); warpCnt[wid][1] = __popc(m1); }
    __syncthreads();
    if (threadIdx.x < 2) {
        int tot = 0;
#pragma unroll
        for (int k = 0; k < 8; k++) tot += warpCnt[k][threadIdx.x];
        baseS[threadIdx.x] = atomicAdd(&g_cnt[threadIdx.x], tot);
    }
    __syncthreads();
    if (valid) {
        int off = baseS[flag];
#pragma unroll
        for (int k = 0; k < 8; k++) if (k < wid) off += warpCnt[k][flag];
        unsigned mm = flag ? m1 : m0;
        off += __popc(mm & ((1u << lane) - 1));
        (flag ? g_listc : g_listv)[off] = i;
    }
}

// ---------------------------------------------------------------------------
// Fused kernel: homogeneous 128-row tiles from the compacted lists.
// smem: A(9216w) B0(9216w) B1(9216w) misc(1024w) = 114688 B; 2 CTAs/SM.
// ---------------------------------------------------------------------------
extern "C" __global__ void __launch_bounds__(256, 2)
fused_kernel(const float* __restrict__ varf, const float* __restrict__ conf,
             const int* __restrict__ assoc,
             const float* __restrict__ vW1, const float* __restrict__ vb1,
             const float* __restrict__ cW1, const float* __restrict__ cb1,
             const float* __restrict__ hb2, const float* __restrict__ hb3,
             const float* __restrict__ W4g, const float* __restrict__ b4g,
             float* __restrict__ out, int n)
{
    extern __shared__ uint32_t smw[];
    uint32_t* A  = smw;
    uint32_t* B0 = smw + TILE_WORDS;
    uint32_t* B1 = smw + 2 * TILE_WORDS;
    float* misc  = (float*)(smw + 3 * TILE_WORDS);
    // misc words: [0]W1(256) [256]b1(128) [384]biasC(128) [512]hb2(128)
    //             [640]F0(128) [768]F1(128)  (part[256] overlays at 640)
    //             [896]rows(int 128)
    float* F0   = misc + 640;
    float* F1   = misc + 768;
    float* part = misc + 640;
    int*   rows = (int*)(misc + 896);

    const int tid = threadIdx.x, lane = tid & 31, w = tid >> 5;
    const int m0w = (w & 3) * 32, n0w = (w >> 2) * 64;
    const int g = lane >> 2, tg = lane & 3;

    const int cnt0 = __ldg(&g_cnt[0]);
    const int cnt1 = n - cnt0;
    const int tiles0 = (cnt0 + 127) >> 7;
    const int tiles1 = (cnt1 + 127) >> 7;
    const int bid = blockIdx.x;
    if (bid >= tiles0 + tiles1) return;
    const int cls  = (bid >= tiles0);
    const int base = (cls ? (bid - tiles0) : bid) << 7;
    const int cnt  = cls ? cnt1 : cnt0;
    const int* list = cls ? g_listc : g_listv;

    const uint32_t B0u = smem_u32(B0), B1u = smem_u32(B1);

    // Prologue: stage comb weights async; load W1/b1/biasC/hb2; gather feats.
    stage_async(B0u, g_wB[cls], tid);
    if (tid < 256) misc[tid] = (cls ? cW1 : vW1)[tid];
    if (tid < 128) {
        misc[256 + tid] = (cls ? cb1 : vb1)[tid];
        misc[384 + tid] = g_biasComb[cls][tid];
        misc[512 + tid] = hb2[tid];
        int idx = base + tid;
        int r = (idx < cnt) ? list[idx] : -1;
        rows[tid] = r;
        float2 f = make_float2(0.f, 0.f);
        if (r >= 0) {
            int srow = g_winner[assoc[r]] & 0x3FFFFFFF;
            f = cls ? ((const float2*)conf)[srow] : ((const float2*)varf)[srow];
        }
        F0[tid] = f.x; F1[tid] = f.y;
    }
    __syncthreads();

    // Layer 1 (fp32, single weight set) -> A permuted bf16x2.
    const float* w1 = misc;
    const float* bb = misc + 256;
    for (int idx = tid; idx < 128 * 8; idx += 256) {
        int m = idx >> 3, c = idx & 7, k0 = c * 16;
        float f0 = F0[m], f1 = F1[m];
        uint32_t wv[8];
#pragma unroll
        for (int u = 0; u < 8; u++) {
            int k = k0 + 2 * u;
            float h0 = fmaxf(fmaf(f0, w1[k],     fmaf(f1, w1[128 + k],     bb[k])),     0.f);
            float h1 = fmaxf(fmaf(f0, w1[k + 1], fmaf(f1, w1[128 + k + 1], bb[k + 1])), 0.f);
            wv[u] = pack_bf16x2(h0, h1);
        }
        uint32_t* dst = A + m * PW + c * 8;
        *(uint4*)(dst)     = make_uint4(wv[0], wv[4], wv[1], wv[5]);
        *(uint4*)(dst + 4) = make_uint4(wv[2], wv[6], wv[3], wv[7]);
    }
    CP_WAIT_ALL();
    __syncthreads();

    float acc[2][8][4];

    // ---- Layer A: GEMM comb (+biasC, ReLU). Stage W2h -> B1 during GEMM.
    stage_async(B1u, g_wB[2], tid);
    ZERO_ACC(acc);
    gemm_frag(A, B0, acc, lane, m0w, n0w);
    __syncthreads();
    {
        const float* bias = misc + 384;
#pragma unroll
        for (int mt = 0; mt < 2; mt++) {
            int row0 = m0w + 16 * mt + g;
            uint32_t* a0 = A + row0 * PW;
            uint32_t* a1 = A + (row0 + 8) * PW;
#pragma unroll
            for (int q = 0; q < 4; q++) {
                int colA = n0w + 16 * q + 2 * tg;
                int colB = colA + 8;
                int wpos = n0w / 2 + 8 * q + 2 * tg;
                uint2 p0, p1;
                p0.x = pack_bf16x2(fmaxf(acc[mt][2*q][0]   + bias[colA], 0.f),
                                   fmaxf(acc[mt][2*q][1]   + bias[colA+1], 0.f));
                p0.y = pack_bf16x2(fmaxf(acc[mt][2*q+1][0] + bias[colB], 0.f),
                                   fmaxf(acc[mt][2*q+1][1] + bias[colB+1], 0.f));
                p1.x = pack_bf16x2(fmaxf(acc[mt][2*q][2]   + bias[colA], 0.f),
                                   fmaxf(acc[mt][2*q][3]   + bias[colA+1], 0.f));
                p1.y = pack_bf16x2(fmaxf(acc[mt][2*q+1][2] + bias[colB], 0.f),
                                   fmaxf(acc[mt][2*q+1][3] + bias[colB+1], 0.f));
                *(uint2*)(a0 + wpos) = p0;
                *(uint2*)(a1 + wpos) = p1;
            }
        }
    }
    CP_WAIT_ALL();
    __syncthreads();

    // ---- Layer B: GEMM W2h (+hb2, ReLU). Stage W3h -> B0 during GEMM.
    stage_async(B0u, g_wB[3], tid);
    ZERO_ACC(acc);
    gemm_frag(A, B1, acc, lane, m0w, n0w);
    __syncthreads();
    {
        const float* bias = misc + 512;
#pragma unroll
        for (int mt = 0; mt < 2; mt++) {
            int row0 = m0w + 16 * mt + g;
            uint32_t* a0 = A + row0 * PW;
            uint32_t* a1 = A + (row0 + 8) * PW;
#pragma unroll
            for (int q = 0; q < 4; q++) {
                int colA = n0w + 16 * q + 2 * tg;
                int colB = colA + 8;
                int wpos = n0w / 2 + 8 * q + 2 * tg;
                uint2 p0, p1;
                p0.x = pack_bf16x2(fmaxf(acc[mt][2*q][0]   + bias[colA], 0.f),
                                   fmaxf(acc[mt][2*q][1]   + bias[colA+1], 0.f));
                p0.y = pack_bf16x2(fmaxf(acc[mt][2*q+1][0] + bias[colB], 0.f),
                                   fmaxf(acc[mt][2*q+1][1] + bias[colB+1], 0.f));
                p1.x = pack_bf16x2(fmaxf(acc[mt][2*q][2]   + bias[colA], 0.f),
                                   fmaxf(acc[mt][2*q][3]   + bias[colA+1], 0.f));
                p1.y = pack_bf16x2(fmaxf(acc[mt][2*q+1][2] + bias[colB], 0.f),
                                   fmaxf(acc[mt][2*q+1][3] + bias[colB+1], 0.f));
                *(uint2*)(a0 + wpos) = p0;
                *(uint2*)(a1 + wpos) = p1;
            }
        }
    }
    CP_WAIT_ALL();
    __syncthreads();

    // ---- Layer C: GEMM W3h; final relu + hb3, W4-dot, sigmoid.
    ZERO_ACC(acc);
    gemm_frag(A, B0, acc, lane, m0w, n0w);
    __syncthreads();   // A/B reads done; part overlays misc F0/F1 region
    {
#pragma unroll
        for (int mt = 0; mt < 2; mt++) {
            float p0 = 0.f, p1 = 0.f;
#pragma unroll
            for (int j = 0; j < 8; j++) {
                int col = n0w + 8 * j + 2 * tg;
                float bA = __ldg(&hb3[col]),     bB = __ldg(&hb3[col + 1]);
                float wA = __ldg(&W4g[col]),     wBv = __ldg(&W4g[col + 1]);
                p0 = fmaf(fmaxf(acc[mt][j][0] + bA, 0.f),  wA,  p0);
                p0 = fmaf(fmaxf(acc[mt][j][1] + bB, 0.f),  wBv, p0);
                p1 = fmaf(fmaxf(acc[mt][j][2] + bA, 0.f),  wA,  p1);
                p1 = fmaf(fmaxf(acc[mt][j][3] + bB, 0.f),  wBv, p1);
            }
            p0 += __shfl_xor_sync(0xffffffffu, p0, 1);
            p0 += __shfl_xor_sync(0xffffffffu, p0, 2);
            p1 += __shfl_xor_sync(0xffffffffu, p1, 1);
            p1 += __shfl_xor_sync(0xffffffffu, p1, 2);
            if (tg == 0) {
                int row0 = m0w + 16 * mt + g;
                part[(w >> 2) * 128 + row0]     = p0;
                part[(w >> 2) * 128 + row0 + 8] = p1;
            }
        }
        __syncthreads();
        if (tid < 128) {
            int r = rows[tid];
            if (r >= 0) {
                float s = part[tid] + part[128 + tid] + __ldg(&b4g[0]);
                out[r] = 1.f / (1.f + expf(-s));
            }
        }
    }
}

// ---------------------------------------------------------------------------
// Launch
// ---------------------------------------------------------------------------
extern "C" void kernel_launch(void* const* d_in, const int* in_sizes, int n_in,
                              void* d_out, int out_size)
{
    (void)n_in; (void)out_size;
    const float* varf      = (const float*)d_in[0];
    const float* conf      = (const float*)d_in[1];
    const int*   assoc_var = (const int*)d_in[3];
    const int*   assoc_con = (const int*)d_in[4];
    const float* vW1 = (const float*)d_in[5];
    const float* vb1 = (const float*)d_in[6];
    const float* vW2 = (const float*)d_in[7];
    const float* vb2 = (const float*)d_in[8];
    const float* cW1 = (const float*)d_in[9];
    const float* cb1 = (const float*)d_in[10];
    const float* cW2 = (const float*)d_in[11];
    const float* cb2 = (const float*)d_in[12];
    const float* W1  = (const float*)d_in[13];
    const float* b1  = (const float*)d_in[14];
    const float* W2  = (const float*)d_in[15];
    const float* b2  = (const float*)d_in[16];
    const float* W3  = (const float*)d_in[17];
    const float* b3  = (const float*)d_in[18];
    const float* W4  = (const float*)d_in[19];
    const float* b4  = (const float*)d_in[20];
    float* out = (float*)d_out;

    const int n_var = in_sizes[0] / 2;
    const int n_con = in_sizes[1] / 2;

    // A + B0 + B1 (3 x 36864 B) + misc (4096 B) = 114688 B/CTA -> 2 CTAs/SM.
    const int smem_bytes = (3 * TILE_WORDS + 1024) * 4;

    cudaFuncSetAttribute(fused_kernel,
                         cudaFuncAttributeMaxDynamicSharedMemorySize, smem_bytes);

    const int gv = (n_var + 127) / 128 + 1;

    reset_kernel<<<1, 32>>>();
    prep_trans<<<64, 256>>>(W2, W3);
    prep_comb<<<64, 256>>>(vW2, cW2, W1);
    prep_bias<<<1, 256>>>(vb2, cb2, W1, b1);
    winner_var_kernel<<<(n_var + 255) / 256, 256>>>(assoc_var, n_var);
    winner_con_kernel<<<(n_con + 255) / 256, 256>>>(assoc_con, n_con);
    compact_kernel<<<(n_var + 255) / 256, 256>>>(assoc_var, n_var);
    fused_kernel<<<gv, 256, smem_bytes>>>(varf, conf, assoc_var,
                                          vW1, vb1, cW1, cb1,
                                          b2, b3, W4, b4, out, n_var);
}

// round 17
// speedup vs baseline: 1.5519x; 1.0288x over previous
#include <cuda_runtime.h>
#include <cuda_bf16.h>
#include <math.h>
#include <stdint.h>

// ---------------------------------------------------------------------------
// Net_76690936037575 — R14 resubmit (prior round was an infra failure; this
// source was never measured). R13 structure with the prep chain collapsed
// into one parallel kernel (prep_all = trans + comb + warp-parallel bias +
// reset).
//   comb_{v,c} = {v,c}W2 @ W1h (fp32 product, one bf16 rounding)
//   bias_{v,c} = {v,c}b2 @ W1h + hb1
// Rows compacted into var-/con-winner lists; homogeneous 128-row tiles.
// Per tile: layer1 (fp32) -> A; GEMM comb (+biasC, ReLU); GEMM W2h (+hb2,
// ReLU); GEMM W3h (+hb3, ReLU, W4-dot, sigmoid). cp.async double-buffered B.
// bf16 mma.sync m16n8k16, permuted-k SMEM word layout (pitch 72 words).
// ---------------------------------------------------------------------------

#define PW 72   // words (bf16x2) per tile row: 64 data + 8 pad
#define TILE_WORDS (128 * PW)   // 9216 words = 36864 B

// Transposed + permuted bf16x2 weights: 0=comb_v^T 1=comb_c^T 2=W2h^T 3=W3h^T
__device__ uint32_t g_wB[4][TILE_WORDS];
// Combined biases: [0]=vb2@W1+b1, [1]=cb2@W1+b1
__device__ float g_biasComb[2][128];
// winner[node] = source row, bit30 set if con.
__device__ int g_winner[1000000u];
// class-compacted output-row lists + counters
__device__ int g_listv[1000000u];
__device__ int g_listc[1000000u];
__device__ int g_cnt[2];

__device__ __forceinline__ uint32_t smem_u32(const void* p) {
    uint32_t a;
    asm("{ .reg .u64 t; cvta.to.shared.u64 t, %1; cvt.u32.u64 %0, t; }" : "=r"(a) : "l"(p));
    return a;
}
__device__ __forceinline__ uint32_t pack_bf16x2(float lo, float hi) {
    uint32_t r;
    asm("cvt.rn.bf16x2.f32 %0, %1, %2;" : "=r"(r) : "f"(hi), "f"(lo));
    return r;
}
__device__ __forceinline__ void mma16(float* d, const uint32_t* a, const uint32_t* b) {
    asm volatile("mma.sync.aligned.m16n8k16.row.col.f32.bf16.bf16.f32 "
                 "{%0,%1,%2,%3}, {%4,%5,%6,%7}, {%8,%9}, {%0,%1,%2,%3};"
                 : "+f"(d[0]), "+f"(d[1]), "+f"(d[2]), "+f"(d[3])
                 : "r"(a[0]), "r"(a[1]), "r"(a[2]), "r"(a[3]),
                   "r"(b[0]), "r"(b[1]));
}

// Warp GEMM 32m x 64n x 128k over permuted bf16x2 word tiles (R9, proven).
__device__ __forceinline__ void gemm_frag(const uint32_t* __restrict__ As,
                                          const uint32_t* __restrict__ Bs,
                                          float acc[2][8][4],
                                          int lane, int m0w, int n0w)
{
    const int g = lane >> 2, tg = lane & 3;
    const uint32_t* Ab = As + (m0w + g) * PW + 2 * tg;
    const uint32_t* Bb = Bs + (n0w + g) * PW + 2 * tg;
#pragma unroll
    for (int kt = 0; kt < 8; kt++) {
        const int k0 = kt * 8;   // words
        uint2 a00 = *(const uint2*)(Ab + k0);
        uint2 a01 = *(const uint2*)(Ab + 8 * PW + k0);
        uint2 a10 = *(const uint2*)(Ab + 16 * PW + k0);
        uint2 a11 = *(const uint2*)(Ab + 24 * PW + k0);
        uint32_t a[2][4];
        a[0][0] = a00.x; a[0][1] = a01.x; a[0][2] = a00.y; a[0][3] = a01.y;
        a[1][0] = a10.x; a[1][1] = a11.x; a[1][2] = a10.y; a[1][3] = a11.y;
        uint32_t b[8][2];
#pragma unroll
        for (int nt = 0; nt < 8; nt++) {
            uint2 bv = *(const uint2*)(Bb + nt * 8 * PW + k0);
            b[nt][0] = bv.x; b[nt][1] = bv.y;
        }
#pragma unroll
        for (int mt = 0; mt < 2; mt++)
#pragma unroll
            for (int nt = 0; nt < 8; nt++)
                mma16(acc[mt][nt], a[mt], b[nt]);
    }
}

// Async weight staging: 2304 x 16B via cp.async (9 per thread), one group.
__device__ __forceinline__ void stage_async(uint32_t Bu, const uint32_t* wt, int tid)
{
    const char* src = (const char*)wt;
#pragma unroll
    for (int i = 0; i < 9; i++) {
        int idx = tid + i * 256;   // < 2304
        asm volatile("cp.async.cg.shared.global [%0], [%1], 16;"
                     :: "r"(Bu + idx * 16), "l"(src + idx * 16) : "memory");
    }
    asm volatile("cp.async.commit_group;" ::: "memory");
}
#define CP_WAIT_ALL() asm volatile("cp.async.wait_group 0;" ::: "memory")

#define ZERO_ACC(acc)                                  \
    _Pragma("unroll") for (int mt = 0; mt < 2; mt++)   \
    _Pragma("unroll") for (int nt = 0; nt < 8; nt++)   \
    _Pragma("unroll") for (int c = 0; c < 4; c++) (acc)[mt][nt][c] = 0.f;

// ---------------------------------------------------------------------------
// prep_all: one kernel, 161 blocks x 256 threads.
//   blocks [0,64)    : W2h/W3h transpose+permute -> g_wB[2],[3]
//   blocks [64,128)  : comb_{v,c} = {v,c}W2 @ W1h -> g_wB[0],[1]
//   blocks [128,160) : bias_{v,c} = {v,c}b2 @ W1h + hb1 (1 warp per output)
//   block  160       : reset g_cnt
// ---------------------------------------------------------------------------
extern "C" __global__ void prep_all(const float* __restrict__ vW2,
                                    const float* __restrict__ cW2,
                                    const float* __restrict__ W1h,
                                    const float* __restrict__ W2h,
                                    const float* __restrict__ W3h,
                                    const float* __restrict__ vb2,
                                    const float* __restrict__ cb2,
                                    const float* __restrict__ hb1)
{
    const int b = blockIdx.x, tid = threadIdx.x;
    if (b < 64) {
        // transpose + permute W2h/W3h
        int idx = b * 256 + tid;           // < 16384
        int w = idx >> 13, e = idx & 8191;
        int nn = e >> 6, u = e & 63;
        const float* src = w ? W3h : W2h;
        int uw = u & 7;
        int pos = (u & ~7) | ((uw & 3) << 1) | (uw >> 2);
        g_wB[2 + w][nn * PW + pos] =
            pack_bf16x2(src[(2 * u) * 128 + nn], src[(2 * u + 1) * 128 + nn]);
    } else if (b < 128) {
        // comb = {v,c}W2 @ W1h (fp32), bf16 once
        int idx = (b - 64) * 256 + tid;    // < 16384
        int w = idx >> 13, e = idx & 8191;
        int nn = e >> 6, u = e & 63;
        const float* src = w ? cW2 : vW2;
        const float* r0 = src + (2 * u) * 128;
        const float* r1 = r0 + 128;
        float d0 = 0.f, d1 = 0.f;
#pragma unroll 4
        for (int j = 0; j < 128; j++) {
            float wj = __ldg(&W1h[j * 128 + nn]);
            d0 = fmaf(r0[j], wj, d0);
            d1 = fmaf(r1[j], wj, d1);
        }
        int uw = u & 7;
        int pos = (u & ~7) | ((uw & 3) << 1) | (uw >> 2);
        g_wB[w][nn * PW + pos] = pack_bf16x2(d0, d1);
    } else if (b < 160) {
        // bias: one warp per output value (256 outputs over 32 blocks)
        int o = (b - 128) * 8 + (tid >> 5);    // 0..255
        int lane = tid & 31;
        int w = o >> 7, nn = o & 127;
        const float* bv = w ? cb2 : vb2;
        float s = 0.f;
#pragma unroll
        for (int t = 0; t < 4; t++) {
            int j = lane + t * 32;
            s = fmaf(__ldg(&bv[j]), __ldg(&W1h[j * 128 + nn]), s);
        }
#pragma unroll
        for (int d = 16; d > 0; d >>= 1) s += __shfl_xor_sync(0xffffffffu, s, d);
        if (lane == 0) g_biasComb[w][nn] = s + __ldg(&hb1[nn]);
    } else {
        if (tid < 2) g_cnt[tid] = 0;
    }
}

// winner build: var pass first, con pass second (con overwrites).
extern "C" __global__ void winner_var_kernel(const int* __restrict__ av, int n)
{
    int i = blockIdx.x * 256 + threadIdx.x;
    if (i < n) g_winner[av[i]] = i;
}
extern "C" __global__ void winner_con_kernel(const int* __restrict__ ac, int n)
{
    int i = blockIdx.x * 256 + threadIdx.x;
    if (i < n) g_winner[ac[i]] = i | (1 << 30);
}

// Block-aggregated class compaction of output rows.
extern "C" __global__ void compact_kernel(const int* __restrict__ av, int n)
{
    __shared__ int warpCnt[8][2];
    __shared__ int baseS[2];
    int i = blockIdx.x * 256 + threadIdx.x;
    int lane = threadIdx.x & 31, wid = threadIdx.x >> 5;
    int valid = (i < n);
    int flag = 0;
    if (valid) flag = (g_winner[av[i]] >> 30) & 1;
    unsigned m1 = __ballot_sync(0xffffffffu, valid && flag);
    unsigned m0 = __ballot_sync(0xffffffffu, valid && !flag);
    if (lane == 0) { warpCnt[wid][0] = __popc(m0); warpCnt[wid][1] = __popc(m1); }
    __syncthreads();
    if (threadIdx.x < 2) {
        int tot = 0;
#pragma unroll
        for (int k = 0; k < 8; k++) tot += warpCnt[k][threadIdx.x];
        baseS[threadIdx.x] = atomicAdd(&g_cnt[threadIdx.x], tot);
    }
    __syncthreads();
    if (valid) {
        int off = baseS[flag];
#pragma unroll
        for (int k = 0; k < 8; k++) if (k < wid) off += warpCnt[k][flag];
        unsigned mm = flag ? m1 : m0;
        off += __popc(mm & ((1u << lane) - 1));
        (flag ? g_listc : g_listv)[off] = i;
    }
}

// ---------------------------------------------------------------------------
// Fused kernel: homogeneous 128-row tiles from the compacted lists.
// smem: A(9216w) B0(9216w) B1(9216w) misc(1024w) = 114688 B; 2 CTAs/SM.
// ---------------------------------------------------------------------------
extern "C" __global__ void __launch_bounds__(256, 2)
fused_kernel(const float* __restrict__ varf, const float* __restrict__ conf,
             const int* __restrict__ assoc,
             const float* __restrict__ vW1, const float* __restrict__ vb1,
             const float* __restrict__ cW1, const float* __restrict__ cb1,
             const float* __restrict__ hb2, const float* __restrict__ hb3,
             const float* __restrict__ W4g, const float* __restrict__ b4g,
             float* __restrict__ out, int n)
{
    extern __shared__ uint32_t smw[];
    uint32_t* A  = smw;
    uint32_t* B0 = smw + TILE_WORDS;
    uint32_t* B1 = smw + 2 * TILE_WORDS;
    float* misc  = (float*)(smw + 3 * TILE_WORDS);
    // misc words: [0]W1(256) [256]b1(128) [384]biasC(128) [512]hb2(128)
    //             [640]F0(128) [768]F1(128)  (part[256] overlays at 640)
    //             [896]rows(int 128)
    float* F0   = misc + 640;
    float* F1   = misc + 768;
    float* part = misc + 640;
    int*   rows = (int*)(misc + 896);

    const int tid = threadIdx.x, lane = tid & 31, w = tid >> 5;
    const int m0w = (w & 3) * 32, n0w = (w >> 2) * 64;
    const int g = lane >> 2, tg = lane & 3;

    const int cnt0 = __ldg(&g_cnt[0]);
    const int cnt1 = n - cnt0;
    const int tiles0 = (cnt0 + 127) >> 7;
    const int tiles1 = (cnt1 + 127) >> 7;
    const int bid = blockIdx.x;
    if (bid >= tiles0 + tiles1) return;
    const int cls  = (bid >= tiles0);
    const int base = (cls ? (bid - tiles0) : bid) << 7;
    const int cnt  = cls ? cnt1 : cnt0;
    const int* list = cls ? g_listc : g_listv;

    const uint32_t B0u = smem_u32(B0), B1u = smem_u32(B1);

    // Prologue: stage comb weights async; load W1/b1/biasC/hb2; gather feats.
    stage_async(B0u, g_wB[cls], tid);
    if (tid < 256) misc[tid] = (cls ? cW1 : vW1)[tid];
    if (tid < 128) {
        misc[256 + tid] = (cls ? cb1 : vb1)[tid];
        misc[384 + tid] = g_biasComb[cls][tid];
        misc[512 + tid] = hb2[tid];
        int idx = base + tid;
        int r = (idx < cnt) ? list[idx] : -1;
        rows[tid] = r;
        float2 f = make_float2(0.f, 0.f);
        if (r >= 0) {
            int srow = g_winner[assoc[r]] & 0x3FFFFFFF;
            f = cls ? ((const float2*)conf)[srow] : ((const float2*)varf)[srow];
        }
        F0[tid] = f.x; F1[tid] = f.y;
    }
    __syncthreads();

    // Layer 1 (fp32, single weight set) -> A permuted bf16x2.
    const float* w1 = misc;
    const float* bb = misc + 256;
    for (int idx = tid; idx < 128 * 8; idx += 256) {
        int m = idx >> 3, c = idx & 7, k0 = c * 16;
        float f0 = F0[m], f1 = F1[m];
        uint32_t wv[8];
#pragma unroll
        for (int u = 0; u < 8; u++) {
            int k = k0 + 2 * u;
            float h0 = fmaxf(fmaf(f0, w1[k],     fmaf(f1, w1[128 + k],     bb[k])),     0.f);
            float h1 = fmaxf(fmaf(f0, w1[k + 1], fmaf(f1, w1[128 + k + 1], bb[k + 1])), 0.f);
            wv[u] = pack_bf16x2(h0, h1);
        }
        uint32_t* dst = A + m * PW + c * 8;
        *(uint4*)(dst)     = make_uint4(wv[0], wv[4], wv[1], wv[5]);
        *(uint4*)(dst + 4) = make_uint4(wv[2], wv[6], wv[3], wv[7]);
    }
    CP_WAIT_ALL();
    __syncthreads();

    float acc[2][8][4];

    // ---- Layer A: GEMM comb (+biasC, ReLU). Stage W2h -> B1 during GEMM.
    stage_async(B1u, g_wB[2], tid);
    ZERO_ACC(acc);
    gemm_frag(A, B0, acc, lane, m0w, n0w);
    __syncthreads();
    {
        const float* bias = misc + 384;
#pragma unroll
        for (int mt = 0; mt < 2; mt++) {
            int row0 = m0w + 16 * mt + g;
            uint32_t* a0 = A + row0 * PW;
            uint32_t* a1 = A + (row0 + 8) * PW;
#pragma unroll
            for (int q = 0; q < 4; q++) {
                int colA = n0w + 16 * q + 2 * tg;
                int colB = colA + 8;
                int wpos = n0w / 2 + 8 * q + 2 * tg;
                uint2 p0, p1;
                p0.x = pack_bf16x2(fmaxf(acc[mt][2*q][0]   + bias[colA], 0.f),
                                   fmaxf(acc[mt][2*q][1]   + bias[colA+1], 0.f));
                p0.y = pack_bf16x2(fmaxf(acc[mt][2*q+1][0] + bias[colB], 0.f),
                                   fmaxf(acc[mt][2*q+1][1] + bias[colB+1], 0.f));
                p1.x = pack_bf16x2(fmaxf(acc[mt][2*q][2]   + bias[colA], 0.f),
                                   fmaxf(acc[mt][2*q][3]   + bias[colA+1], 0.f));
                p1.y = pack_bf16x2(fmaxf(acc[mt][2*q+1][2] + bias[colB], 0.f),
                                   fmaxf(acc[mt][2*q+1][3] + bias[colB+1], 0.f));
                *(uint2*)(a0 + wpos) = p0;
                *(uint2*)(a1 + wpos) = p1;
            }
        }
    }
    CP_WAIT_ALL();
    __syncthreads();

    // ---- Layer B: GEMM W2h (+hb2, ReLU). Stage W3h -> B0 during GEMM.
    stage_async(B0u, g_wB[3], tid);
    ZERO_ACC(acc);
    gemm_frag(A, B1, acc, lane, m0w, n0w);
    __syncthreads();
    {
        const float* bias = misc + 512;
#pragma unroll
        for (int mt = 0; mt < 2; mt++) {
            int row0 = m0w + 16 * mt + g;
            uint32_t* a0 = A + row0 * PW;
            uint32_t* a1 = A + (row0 + 8) * PW;
#pragma unroll
            for (int q = 0; q < 4; q++) {
                int colA = n0w + 16 * q + 2 * tg;
                int colB = colA + 8;
                int wpos = n0w / 2 + 8 * q + 2 * tg;
                uint2 p0, p1;
                p0.x = pack_bf16x2(fmaxf(acc[mt][2*q][0]   + bias[colA], 0.f),
                                   fmaxf(acc[mt][2*q][1]   + bias[colA+1], 0.f));
                p0.y = pack_bf16x2(fmaxf(acc[mt][2*q+1][0] + bias[colB], 0.f),
                                   fmaxf(acc[mt][2*q+1][1] + bias[colB+1], 0.f));
                p1.x = pack_bf16x2(fmaxf(acc[mt][2*q][2]   + bias[colA], 0.f),
                                   fmaxf(acc[mt][2*q][3]   + bias[colA+1], 0.f));
                p1.y = pack_bf16x2(fmaxf(acc[mt][2*q+1][2] + bias[colB], 0.f),
                                   fmaxf(acc[mt][2*q+1][3] + bias[colB+1], 0.f));
                *(uint2*)(a0 + wpos) = p0;
                *(uint2*)(a1 + wpos) = p1;
            }
        }
    }
    CP_WAIT_ALL();
    __syncthreads();

    // ---- Layer C: GEMM W3h; final relu + hb3, W4-dot, sigmoid.
    ZERO_ACC(acc);
    gemm_frag(A, B0, acc, lane, m0w, n0w);
    __syncthreads();   // A/B reads done; part overlays misc F0/F1 region
    {
#pragma unroll
        for (int mt = 0; mt < 2; mt++) {
            float p0 = 0.f, p1 = 0.f;
#pragma unroll
            for (int j = 0; j < 8; j++) {
                int col = n0w + 8 * j + 2 * tg;
                float bA = __ldg(&hb3[col]),     bB = __ldg(&hb3[col + 1]);
                float wA = __ldg(&W4g[col]),     wBv = __ldg(&W4g[col + 1]);
                p0 = fmaf(fmaxf(acc[mt][j][0] + bA, 0.f),  wA,  p0);
                p0 = fmaf(fmaxf(acc[mt][j][1] + bB, 0.f),  wBv, p0);
                p1 = fmaf(fmaxf(acc[mt][j][2] + bA, 0.f),  wA,  p1);
                p1 = fmaf(fmaxf(acc[mt][j][3] + bB, 0.f),  wBv, p1);
            }
            p0 += __shfl_xor_sync(0xffffffffu, p0, 1);
            p0 += __shfl_xor_sync(0xffffffffu, p0, 2);
            p1 += __shfl_xor_sync(0xffffffffu, p1, 1);
            p1 += __shfl_xor_sync(0xffffffffu, p1, 2);
            if (tg == 0) {
                int row0 = m0w + 16 * mt + g;
                part[(w >> 2) * 128 + row0]     = p0;
                part[(w >> 2) * 128 + row0 + 8] = p1;
            }
        }
        __syncthreads();
        if (tid < 128) {
            int r = rows[tid];
            if (r >= 0) {
                float s = part[tid] + part[128 + tid] + __ldg(&b4g[0]);
                out[r] = 1.f / (1.f + expf(-s));
            }
        }
    }
}

// ---------------------------------------------------------------------------
// Launch
// ---------------------------------------------------------------------------
extern "C" void kernel_launch(void* const* d_in, const int* in_sizes, int n_in,
                              void* d_out, int out_size)
{
    (void)n_in; (void)out_size;
    const float* varf      = (const float*)d_in[0];
    const float* conf      = (const float*)d_in[1];
    const int*   assoc_var = (const int*)d_in[3];
    const int*   assoc_con = (const int*)d_in[4];
    const float* vW1 = (const float*)d_in[5];
    const float* vb1 = (const float*)d_in[6];
    const float* vW2 = (const float*)d_in[7];
    const float* vb2 = (const float*)d_in[8];
    const float* cW1 = (const float*)d_in[9];
    const float* cb1 = (const float*)d_in[10];
    const float* cW2 = (const float*)d_in[11];
    const float* cb2 = (const float*)d_in[12];
    const float* W1  = (const float*)d_in[13];
    const float* b1  = (const float*)d_in[14];
    const float* W2  = (const float*)d_in[15];
    const float* b2  = (const float*)d_in[16];
    const float* W3  = (const float*)d_in[17];
    const float* b3  = (const float*)d_in[18];
    const float* W4  = (const float*)d_in[19];
    const float* b4  = (const float*)d_in[20];
    float* out = (float*)d_out;

    const int n_var = in_sizes[0] / 2;
    const int n_con = in_sizes[1] / 2;

    // A + B0 + B1 (3 x 36864 B) + misc (4096 B) = 114688 B/CTA -> 2 CTAs/SM.
    const int smem_bytes = (3 * TILE_WORDS + 1024) * 4;

    cudaFuncSetAttribute(fused_kernel,
                         cudaFuncAttributeMaxDynamicSharedMemorySize, smem_bytes);

    const int gv = (n_var + 127) / 128 + 1;

    prep_all<<<161, 256>>>(vW2, cW2, W1, W2, W3, vb2, cb2, b1);
    winner_var_kernel<<<(n_var + 255) / 256, 256>>>(assoc_var, n_var);
    winner_con_kernel<<<(n_con + 255) / 256, 256>>>(assoc_con, n_con);
    compact_kernel<<<(n_var + 255) / 256, 256>>>(assoc_var, n_var);
    fused_kernel<<<gv, 256, smem_bytes>>>(varf, conf, assoc_var,
                                          vW1, vb1, cW1, cb1,
                                          b2, b3, W4, b4, out, n_var);
}